// round 7
// baseline (speedup 1.0000x reference)
#include <cuda_runtime.h>
#include <math.h>
#include <stdint.h>

#define Bq 16
#define Nq 512
#define Dq 768
#define Hq 12
#define DKq 64
#define TOK (Bq*Nq)   // 8192

// Scratch
__device__ float g_x[TOK*Dq];        // layernormed, tf32-rounded
__device__ float g_q[TOK*Dq];        // (B,N,H,DK) fp32
__device__ float g_k[TOK*Dq];
__device__ float g_v[TOK*Dq];
__device__ float g_o[TOK*Dq];        // attention out, tf32-rounded
__device__ float g_wq[Dq*Dq];        // tf32-rounded weights
__device__ float g_wk[Dq*Dq];
__device__ float g_wv[Dq*Dq];
__device__ float g_wo[Dq*Dq];
__device__ float g_px[TOK];
__device__ float g_py[TOK];
__device__ int   g_btab[201];

// single dynamic shared buffer shared across kernels
extern __shared__ uint4 dynsm[];

// ---------------------------------------------------------------------------
// helpers
// ---------------------------------------------------------------------------
__device__ __forceinline__ float f2tf32f(float f) {
    uint32_t u;
    asm("cvt.rna.tf32.f32 %0, %1;" : "=r"(u) : "f"(f));
    return __uint_as_float(u);
}
__device__ __forceinline__ void mma_tf32(float c[4], const uint32_t a[4], const uint32_t b[2]) {
    asm volatile(
        "mma.sync.aligned.m16n8k8.row.col.f32.tf32.tf32.f32 "
        "{%0,%1,%2,%3}, {%4,%5,%6,%7}, {%8,%9}, {%0,%1,%2,%3};"
        : "+f"(c[0]), "+f"(c[1]), "+f"(c[2]), "+f"(c[3])
        : "r"(a[0]), "r"(a[1]), "r"(a[2]), "r"(a[3]), "r"(b[0]), "r"(b[1]));
}
__device__ __forceinline__ void cp16(void* smem, const void* g) {
    uint32_t sa = (uint32_t)__cvta_generic_to_shared(smem);
    asm volatile("cp.async.ca.shared.global [%0], [%1], 16;" :: "r"(sa), "l"(g));
}
__device__ __forceinline__ void cp_commit() {
    asm volatile("cp.async.commit_group;" ::: "memory");
}
__device__ __forceinline__ void cp_wait1() {
    asm volatile("cp.async.wait_group 1;" ::: "memory");
}
__device__ __forceinline__ void cp_wait0() {
    asm volatile("cp.async.wait_group 0;" ::: "memory");
}

// ---------------------------------------------------------------------------
// tf32 mma.sync GEMM (operands pre-rounded to tf32): C = A @ W^T + bias
// CTA tile 128x128, KC=32, cp.async double buffer. grid.z selects W/bias/C.
// ---------------------------------------------------------------------------
#define KC 32
#define LDT 40
#define STAGE (128 * LDT)   // uint32s per matrix per stage

__global__ void __launch_bounds__(256) hmma_gemm(const float* __restrict__ A0,
                                                 const float* __restrict__ W0,
                                                 const float* __restrict__ b0,
                                                 float* __restrict__ C0,
                                                 const float* __restrict__ W1,
                                                 const float* __restrict__ b1,
                                                 float* __restrict__ C1,
                                                 const float* __restrict__ W2,
                                                 const float* __restrict__ b2,
                                                 float* __restrict__ C2) {
    uint32_t* sm = (uint32_t*)dynsm;
    // layout: [stage0 A][stage0 W][stage1 A][stage1 W]
    int z = blockIdx.z;
    const float* A = A0;
    const float* W = (z == 0) ? W0 : (z == 1) ? W1 : W2;
    const float* bias = (z == 0) ? b0 : (z == 1) ? b1 : b2;
    float* C = (z == 0) ? C0 : (z == 1) ? C1 : C2;

    int tid = threadIdx.x;
    int wid = tid >> 5, lane = tid & 31;
    int wm = (wid >> 1) * 32;
    int wn = (wid & 1) * 64;
    int gid = lane >> 2;
    int lig = lane & 3;
    int m0 = blockIdx.y * 128, n0 = blockIdx.x * 128;

    const float* Ap = A + (size_t)m0 * Dq;
    const float* Wp = W + (size_t)n0 * Dq;

    int lr = tid >> 1;               // 0..127
    int lc = (tid & 1) * 16;         // 0 or 16

    float acc[2][8][4];
    #pragma unroll
    for (int mi = 0; mi < 2; mi++)
        #pragma unroll
        for (int ni = 0; ni < 8; ni++)
            #pragma unroll
            for (int j = 0; j < 4; j++) acc[mi][ni][j] = 0.f;

    // prologue: stage 0 <- chunk 0
    {
        uint32_t* As = sm;
        uint32_t* Ws = sm + STAGE;
        #pragma unroll
        for (int v = 0; v < 4; v++) {
            int c4 = lc + v * 4;
            cp16(&As[lr * LDT + c4], Ap + (size_t)lr * Dq + c4);
            cp16(&Ws[lr * LDT + c4], Wp + (size_t)lr * Dq + c4);
        }
        cp_commit();
    }

    const int NCH = Dq / KC;  // 24
    for (int c = 0; c < NCH; c++) {
        int cur = c & 1;
        if (c + 1 < NCH) {
            uint32_t* As = sm + ((c + 1) & 1) * 2 * STAGE;
            uint32_t* Ws = As + STAGE;
            int k0 = (c + 1) * KC;
            #pragma unroll
            for (int v = 0; v < 4; v++) {
                int c4 = lc + v * 4;
                cp16(&As[lr * LDT + c4], Ap + (size_t)lr * Dq + k0 + c4);
                cp16(&Ws[lr * LDT + c4], Wp + (size_t)lr * Dq + k0 + c4);
            }
            cp_commit();
            cp_wait1();
        } else {
            cp_wait0();
        }
        __syncthreads();
        uint32_t* As = sm + cur * 2 * STAGE;
        uint32_t* Ws = As + STAGE;
        #pragma unroll
        for (int ks = 0; ks < KC / 8; ks++) {
            int k8 = ks * 8;
            uint32_t afr[2][4];
            #pragma unroll
            for (int mi = 0; mi < 2; mi++) {
                int rb = wm + mi * 16;
                afr[mi][0] = As[(rb + gid) * LDT + k8 + lig];
                afr[mi][1] = As[(rb + 8 + gid) * LDT + k8 + lig];
                afr[mi][2] = As[(rb + gid) * LDT + k8 + 4 + lig];
                afr[mi][3] = As[(rb + 8 + gid) * LDT + k8 + 4 + lig];
            }
            #pragma unroll
            for (int ni = 0; ni < 8; ni++) {
                uint32_t bfr[2];
                int nb = wn + ni * 8;
                bfr[0] = Ws[(nb + gid) * LDT + k8 + lig];
                bfr[1] = Ws[(nb + gid) * LDT + k8 + 4 + lig];
                mma_tf32(acc[0][ni], afr[0], bfr);
                mma_tf32(acc[1][ni], afr[1], bfr);
            }
        }
        __syncthreads();
    }

    #pragma unroll
    for (int mi = 0; mi < 2; mi++) {
        int rbase = m0 + wm + mi * 16 + gid;
        #pragma unroll
        for (int ni = 0; ni < 8; ni++) {
            int col = n0 + wn + ni * 8 + 2 * lig;
            float bb0 = bias[col], bb1 = bias[col + 1];
            float* p0 = C + (size_t)rbase * Dq + col;
            float* p1 = C + (size_t)(rbase + 8) * Dq + col;
            float2 o0 = {acc[mi][ni][0] + bb0, acc[mi][ni][1] + bb1};
            float2 o1 = {acc[mi][ni][2] + bb0, acc[mi][ni][3] + bb1};
            *(float2*)p0 = o0;
            *(float2*)p1 = o1;
        }
    }
}

// ---------------------------------------------------------------------------
// Fused attention: per CTA (bh, 32 q rows): QK^T + bias -> softmax -> att
// write -> AV -> g_o (tf32-rounded).
// ---------------------------------------------------------------------------
#define QT 32
#define SLD 520    // S row stride (floats)
#define KLD 68     // K/V tile stride
#define QLD 34     // Qt stride

#define OFF_QT  (QT * SLD)
#define OFF_KV  (OFF_QT + 64 * QLD)
#define OFF_PXK (OFF_KV + 64 * KLD)
#define OFF_PYK (OFF_PXK + 512)
#define OFF_PXQ (OFF_PYK + 512)
#define OFF_PYQ (OFF_PXQ + QT)
#define OFF_BT  (OFF_PYQ + QT)
#define ATT_SMEM ((OFF_BT + 201 + 3) * 4)

__global__ void __launch_bounds__(256, 2) attn_fused(const float* __restrict__ dist_emb,
                                                     float* __restrict__ att) {
    float* sm = (float*)dynsm;
    float* S   = sm;
    float* Qt  = sm + OFF_QT;
    float* KV  = sm + OFF_KV;
    float* pxk = sm + OFF_PXK;
    float* pyk = sm + OFF_PYK;
    float* pxq = sm + OFF_PXQ;
    float* pyq = sm + OFF_PYQ;
    float* bt  = sm + OFF_BT;

    int bh = blockIdx.y;
    int b = bh / Hq, h = bh - b * Hq;
    int q0 = blockIdx.x * QT;
    int tid = threadIdx.x;
    int wid = tid >> 5, lane = tid & 31;
    int ty = tid >> 4, tx = tid & 15;

    // load Q tile transposed: Qt[d][q]
    for (int i = tid; i < QT * 16; i += 256) {
        int r = i >> 4, c = (i & 15) * 4;
        float4 v = *(const float4*)(g_q + ((size_t)((b * Nq + q0 + r) * Hq + h)) * DKq + c);
        Qt[(c + 0) * QLD + r] = v.x;
        Qt[(c + 1) * QLD + r] = v.y;
        Qt[(c + 2) * QLD + r] = v.z;
        Qt[(c + 3) * QLD + r] = v.w;
    }
    for (int i = tid; i < Nq; i += 256) {
        pxk[i] = g_px[b * Nq + i];
        pyk[i] = g_py[b * Nq + i];
    }
    if (tid < QT) {
        pxq[tid] = g_px[b * Nq + q0 + tid];
        pyq[tid] = g_py[b * Nq + q0 + tid];
    }
    for (int i = tid; i < 201; i += 256)
        bt[i] = dist_emb[g_btab[i] * Hq + h];

    // ---- QK^T + bias into S ----
    for (int kc = 0; kc < 8; kc++) {
        __syncthreads();
        // load K chunk transposed: KV[d][kseq_local]
        for (int i = tid; i < 64 * 16; i += 256) {
            int r = i >> 4, c = (i & 15) * 4;
            float4 v = *(const float4*)(g_k + ((size_t)((b * Nq + kc * 64 + r) * Hq + h)) * DKq + c);
            KV[(c + 0) * KLD + r] = v.x;
            KV[(c + 1) * KLD + r] = v.y;
            KV[(c + 2) * KLD + r] = v.z;
            KV[(c + 3) * KLD + r] = v.w;
        }
        __syncthreads();
        float acc[2][4] = {};
        #pragma unroll 4
        for (int kk = 0; kk < 64; kk++) {
            float2 a = *(const float2*)&Qt[kk * QLD + ty * 2];
            float4 bv = *(const float4*)&KV[kk * KLD + tx * 4];
            acc[0][0] = fmaf(a.x, bv.x, acc[0][0]);
            acc[0][1] = fmaf(a.x, bv.y, acc[0][1]);
            acc[0][2] = fmaf(a.x, bv.z, acc[0][2]);
            acc[0][3] = fmaf(a.x, bv.w, acc[0][3]);
            acc[1][0] = fmaf(a.y, bv.x, acc[1][0]);
            acc[1][1] = fmaf(a.y, bv.y, acc[1][1]);
            acc[1][2] = fmaf(a.y, bv.z, acc[1][2]);
            acc[1][3] = fmaf(a.y, bv.w, acc[1][3]);
        }
        #pragma unroll
        for (int i = 0; i < 2; i++) {
            int q = ty * 2 + i;
            float pxi = pxq[q], pyi = pyq[q];
            #pragma unroll
            for (int j = 0; j < 4; j++) {
                int k = kc * 64 + tx * 4 + j;
                float dx = pxk[k] - pxi;
                float dy = pyk[k] - pyi;
                int d2 = (int)(dx * dx + dy * dy);
                S[q * SLD + k] = acc[i][j] * 0.125f + bt[d2];
            }
        }
    }
    __syncthreads();

    // ---- softmax rows (8 warps x 4 rows), write att ----
    #pragma unroll
    for (int rr = 0; rr < 4; rr++) {
        int q = wid * 4 + rr;
        float vals[16];
        float m = -1e30f;
        #pragma unroll
        for (int j = 0; j < 16; j++) {
            vals[j] = S[q * SLD + lane + j * 32];
            m = fmaxf(m, vals[j]);
        }
        #pragma unroll
        for (int o = 16; o > 0; o >>= 1) m = fmaxf(m, __shfl_xor_sync(0xffffffffu, m, o));
        float s = 0.f;
        #pragma unroll
        for (int j = 0; j < 16; j++) {
            vals[j] = __expf(vals[j] - m);
            s += vals[j];
        }
        #pragma unroll
        for (int o = 16; o > 0; o >>= 1) s += __shfl_xor_sync(0xffffffffu, s, o);
        float inv = 1.0f / s;
        float* arow = att + (((size_t)bh) * Nq + q0 + q) * Nq;
        #pragma unroll
        for (int j = 0; j < 16; j++) {
            float v = vals[j] * inv;
            S[q * SLD + lane + j * 32] = v;
            arow[lane + j * 32] = v;
        }
    }

    // ---- AV: out[q][d] = sum_k S[q][k] * V[k][d] ----
    float o[2][4] = {};
    for (int kc = 0; kc < 8; kc++) {
        __syncthreads();
        for (int i = tid; i < 64 * 16; i += 256) {
            int r = i >> 4, c = (i & 15) * 4;
            float4 v = *(const float4*)(g_v + ((size_t)((b * Nq + kc * 64 + r) * Hq + h)) * DKq + c);
            *(float4*)&KV[r * KLD + c] = v;
        }
        __syncthreads();
        #pragma unroll 4
        for (int kk = 0; kk < 64; kk++) {
            float a0 = S[(ty * 2 + 0) * SLD + kc * 64 + kk];
            float a1 = S[(ty * 2 + 1) * SLD + kc * 64 + kk];
            float4 bv = *(const float4*)&KV[kk * KLD + tx * 4];
            o[0][0] = fmaf(a0, bv.x, o[0][0]);
            o[0][1] = fmaf(a0, bv.y, o[0][1]);
            o[0][2] = fmaf(a0, bv.z, o[0][2]);
            o[0][3] = fmaf(a0, bv.w, o[0][3]);
            o[1][0] = fmaf(a1, bv.x, o[1][0]);
            o[1][1] = fmaf(a1, bv.y, o[1][1]);
            o[1][2] = fmaf(a1, bv.z, o[1][2]);
            o[1][3] = fmaf(a1, bv.w, o[1][3]);
        }
    }
    #pragma unroll
    for (int i = 0; i < 2; i++) {
        int q = q0 + ty * 2 + i;
        float4 ov;
        ov.x = f2tf32f(o[i][0]); ov.y = f2tf32f(o[i][1]);
        ov.z = f2tf32f(o[i][2]); ov.w = f2tf32f(o[i][3]);
        *(float4*)(g_o + ((size_t)((b * Nq + q) * Hq + h)) * DKq + tx * 4) = ov;
    }
}

// ---------------------------------------------------------------------------
// LayerNorm -> tf32-rounded g_x
// ---------------------------------------------------------------------------
__global__ void __launch_bounds__(256) ln_kernel(const float* __restrict__ f,
                                                 const float* __restrict__ gamma,
                                                 const float* __restrict__ beta) {
    int t = blockIdx.x;
    const float* in = f + (size_t)t * Dq;
    float* out = g_x + (size_t)t * Dq;
    int tid = threadIdx.x;
    float v0 = in[tid], v1 = in[tid + 256], v2 = in[tid + 512];

    __shared__ float red[8];
    __shared__ float bc;

    float s = v0 + v1 + v2;
    #pragma unroll
    for (int o = 16; o > 0; o >>= 1) s += __shfl_down_sync(0xffffffffu, s, o);
    if ((tid & 31) == 0) red[tid >> 5] = s;
    __syncthreads();
    if (tid == 0) {
        float tot = 0.f;
        #pragma unroll
        for (int i = 0; i < 8; i++) tot += red[i];
        bc = tot * (1.0f / 768.0f);
    }
    __syncthreads();
    float mean = bc;
    float d0 = v0 - mean, d1 = v1 - mean, d2 = v2 - mean;
    float ss = d0 * d0 + d1 * d1 + d2 * d2;
    #pragma unroll
    for (int o = 16; o > 0; o >>= 1) ss += __shfl_down_sync(0xffffffffu, ss, o);
    __syncthreads();
    if ((tid & 31) == 0) red[tid >> 5] = ss;
    __syncthreads();
    if (tid == 0) {
        float tot = 0.f;
        #pragma unroll
        for (int i = 0; i < 8; i++) tot += red[i];
        bc = tot * (1.0f / 768.0f);
    }
    __syncthreads();
    float inv = rsqrtf(bc + 1e-5f);
    out[tid]       = f2tf32f(d0 * inv * gamma[tid]       + beta[tid]);
    out[tid + 256] = f2tf32f(d1 * inv * gamma[tid + 256] + beta[tid + 256]);
    out[tid + 512] = f2tf32f(d2 * inv * gamma[tid + 512] + beta[tid + 512]);
}

// ---------------------------------------------------------------------------
// Convert 4 weight matrices to tf32-rounded copies
// ---------------------------------------------------------------------------
__global__ void __launch_bounds__(256) cvtw_kernel(const float* __restrict__ Wq,
                                                   const float* __restrict__ Wk,
                                                   const float* __restrict__ Wv,
                                                   const float* __restrict__ Wo) {
    int i = blockIdx.x * 256 + threadIdx.x;
    if (i >= Dq * Dq) return;
    g_wq[i] = f2tf32f(Wq[i]);
    g_wk[i] = f2tf32f(Wk[i]);
    g_wv[i] = f2tf32f(Wv[i]);
    g_wo[i] = f2tf32f(Wo[i]);
}

// ---------------------------------------------------------------------------
// Patch bins
// ---------------------------------------------------------------------------
__global__ void __launch_bounds__(256) bins_kernel(const float* __restrict__ boxes,
                                                   const int* __restrict__ im) {
    int idx = blockIdx.x * blockDim.x + threadIdx.x;
    if (idx < 201) g_btab[idx] = (int)(2.0 * sqrt((double)idx));
    if (idx >= TOK) return;
    int b = idx / Nq;
    float wf = (float)im[b * 4 + 0];
    float hf = (float)im[b * 4 + 1];
    const float* bx = boxes + (size_t)idx * 4;
    float x1 = bx[0] * wf, y1 = bx[1] * hf, x2 = bx[2] * wf, y2 = bx[3] * hf;
    float spw = floorf(wf / 11.0f), sph = floorf(hf / 11.0f);
    float cx = floorf((x1 + x2) / 2.0f), cy = floorf((y1 + y2) / 2.0f);
    int px = 0, py = 0;
    #pragma unroll
    for (int i = 0; i < 11; i++) {
        float lo = (float)i * spw, hi = (float)(i + 1) * spw;
        if (lo <= cx && cx <= hi) { px = i; break; }
    }
    #pragma unroll
    for (int i = 0; i < 11; i++) {
        float lo = (float)i * sph, hi = (float)(i + 1) * sph;
        if (lo <= cy && cy <= hi) { py = i; break; }
    }
    g_px[idx] = (float)px;
    g_py[idx] = (float)py;
}

// ---------------------------------------------------------------------------
extern "C" void kernel_launch(void* const* d_in, const int* in_sizes, int n_in,
                              void* d_out, int out_size) {
    const float* features = (const float*)d_in[0];
    const float* boxes    = (const float*)d_in[1];
    const int*   im       = (const int*)d_in[2];
    const float* Wq = (const float*)d_in[3];  const float* bqv = (const float*)d_in[4];
    const float* Wk = (const float*)d_in[5];  const float* bkv = (const float*)d_in[6];
    const float* Wv = (const float*)d_in[7];  const float* bvv = (const float*)d_in[8];
    const float* Wo = (const float*)d_in[9];  const float* bov = (const float*)d_in[10];
    const float* gamma = (const float*)d_in[11];
    const float* beta  = (const float*)d_in[12];
    const float* demb  = (const float*)d_in[13];

    float* out = (float*)d_out;
    float* att = out + (size_t)TOK * Dq;

    void *px_, *pq_, *pk_, *pv_, *po_, *pwq_, *pwk_, *pwv_, *pwo_;
    cudaGetSymbolAddress(&px_, g_x);
    cudaGetSymbolAddress(&pq_, g_q);
    cudaGetSymbolAddress(&pk_, g_k);
    cudaGetSymbolAddress(&pv_, g_v);
    cudaGetSymbolAddress(&po_, g_o);
    cudaGetSymbolAddress(&pwq_, g_wq);
    cudaGetSymbolAddress(&pwk_, g_wk);
    cudaGetSymbolAddress(&pwv_, g_wv);
    cudaGetSymbolAddress(&pwo_, g_wo);

    static int attr_done = 0;
    const int GEMM_SMEM = 4 * STAGE * 4;   // 81920 B
    if (!attr_done) {
        cudaFuncSetAttribute(hmma_gemm, cudaFuncAttributeMaxDynamicSharedMemorySize, GEMM_SMEM);
        cudaFuncSetAttribute(attn_fused, cudaFuncAttributeMaxDynamicSharedMemorySize, ATT_SMEM);
        attr_done = 1;
    }

    ln_kernel<<<TOK, 256>>>(features, gamma, beta);
    bins_kernel<<<(TOK + 255) / 256, 256>>>(boxes, im);
    cvtw_kernel<<<(Dq * Dq + 255) / 256, 256>>>(Wq, Wk, Wv, Wo);

    // QKV projections in one launch
    dim3 gqkv(Dq / 128, TOK / 128, 3);
    hmma_gemm<<<gqkv, 256, GEMM_SMEM>>>(
        (const float*)px_,
        (const float*)pwq_, bqv, (float*)pq_,
        (const float*)pwk_, bkv, (float*)pk_,
        (const float*)pwv_, bvv, (float*)pv_);

    // Fused attention
    attn_fused<<<dim3(Nq / QT, Bq * Hq), 256, ATT_SMEM>>>(demb, att);

    // Output projection
    dim3 gout(Dq / 128, TOK / 128, 1);
    hmma_gemm<<<gout, 256, GEMM_SMEM>>>(
        (const float*)po_,
        (const float*)pwo_, bov, out,
        (const float*)pwo_, bov, out,
        (const float*)pwo_, bov, out);
}

// round 9
// speedup vs baseline: 1.9898x; 1.9898x over previous
#include <cuda_runtime.h>
#include <math.h>
#include <stdint.h>

#define Bq 16
#define Nq 512
#define Dq 768
#define Hq 12
#define DKq 64
#define TOK (Bq*Nq)   // 8192

// Scratch
__device__ float g_x[TOK*Dq];        // layernormed, tf32-rounded
__device__ float g_q[TOK*Dq];        // (B,N,H,DK) fp32
__device__ float g_k[TOK*Dq];
__device__ float g_v[TOK*Dq];
__device__ float g_o[TOK*Dq];        // attention out, tf32-rounded
__device__ float g_wq[Dq*Dq];        // tf32-rounded weights
__device__ float g_wk[Dq*Dq];
__device__ float g_wv[Dq*Dq];
__device__ float g_wo[Dq*Dq];
__device__ float g_px[TOK];
__device__ float g_py[TOK];
__device__ int   g_btab[201];

// single dynamic shared buffer shared across kernels
extern __shared__ uint4 dynsm[];

// ---------------------------------------------------------------------------
// helpers
// ---------------------------------------------------------------------------
__device__ __forceinline__ float f2tf32f(float f) {
    uint32_t u;
    asm("cvt.rna.tf32.f32 %0, %1;" : "=r"(u) : "f"(f));
    return __uint_as_float(u);
}
__device__ __forceinline__ uint32_t f2tf32u(float f) {
    uint32_t u;
    asm("cvt.rna.tf32.f32 %0, %1;" : "=r"(u) : "f"(f));
    return u;
}
__device__ __forceinline__ void mma_tf32(float c[4], const uint32_t a[4], const uint32_t b[2]) {
    asm volatile(
        "mma.sync.aligned.m16n8k8.row.col.f32.tf32.tf32.f32 "
        "{%0,%1,%2,%3}, {%4,%5,%6,%7}, {%8,%9}, {%0,%1,%2,%3};"
        : "+f"(c[0]), "+f"(c[1]), "+f"(c[2]), "+f"(c[3])
        : "r"(a[0]), "r"(a[1]), "r"(a[2]), "r"(a[3]), "r"(b[0]), "r"(b[1]));
}
__device__ __forceinline__ void cp16(void* smem, const void* g) {
    uint32_t sa = (uint32_t)__cvta_generic_to_shared(smem);
    asm volatile("cp.async.ca.shared.global [%0], [%1], 16;" :: "r"(sa), "l"(g));
}
__device__ __forceinline__ void cp_commit() {
    asm volatile("cp.async.commit_group;" ::: "memory");
}
__device__ __forceinline__ void cp_wait1() {
    asm volatile("cp.async.wait_group 1;" ::: "memory");
}
__device__ __forceinline__ void cp_wait0() {
    asm volatile("cp.async.wait_group 0;" ::: "memory");
}

// ---------------------------------------------------------------------------
// tf32 mma.sync GEMM (operands pre-rounded to tf32): C = A @ W^T + bias
// CTA tile 128x128, KC=32, cp.async double buffer. grid.z selects W/bias/C.
// ---------------------------------------------------------------------------
#define KC 32
#define LDT 40
#define STAGE (128 * LDT)   // uint32s per matrix per stage

__global__ void __launch_bounds__(256) hmma_gemm(const float* __restrict__ A0,
                                                 const float* __restrict__ W0,
                                                 const float* __restrict__ b0,
                                                 float* __restrict__ C0,
                                                 const float* __restrict__ W1,
                                                 const float* __restrict__ b1,
                                                 float* __restrict__ C1,
                                                 const float* __restrict__ W2,
                                                 const float* __restrict__ b2,
                                                 float* __restrict__ C2) {
    uint32_t* sm = (uint32_t*)dynsm;
    int z = blockIdx.z;
    const float* A = A0;
    const float* W = (z == 0) ? W0 : (z == 1) ? W1 : W2;
    const float* bias = (z == 0) ? b0 : (z == 1) ? b1 : b2;
    float* C = (z == 0) ? C0 : (z == 1) ? C1 : C2;

    int tid = threadIdx.x;
    int wid = tid >> 5, lane = tid & 31;
    int wm = (wid >> 1) * 32;
    int wn = (wid & 1) * 64;
    int gid = lane >> 2;
    int lig = lane & 3;
    int m0 = blockIdx.y * 128, n0 = blockIdx.x * 128;

    const float* Ap = A + (size_t)m0 * Dq;
    const float* Wp = W + (size_t)n0 * Dq;

    int lr = tid >> 1;
    int lc = (tid & 1) * 16;

    float acc[2][8][4];
    #pragma unroll
    for (int mi = 0; mi < 2; mi++)
        #pragma unroll
        for (int ni = 0; ni < 8; ni++)
            #pragma unroll
            for (int j = 0; j < 4; j++) acc[mi][ni][j] = 0.f;

    {
        uint32_t* As = sm;
        uint32_t* Ws = sm + STAGE;
        #pragma unroll
        for (int v = 0; v < 4; v++) {
            int c4 = lc + v * 4;
            cp16(&As[lr * LDT + c4], Ap + (size_t)lr * Dq + c4);
            cp16(&Ws[lr * LDT + c4], Wp + (size_t)lr * Dq + c4);
        }
        cp_commit();
    }

    const int NCH = Dq / KC;  // 24
    for (int c = 0; c < NCH; c++) {
        int cur = c & 1;
        if (c + 1 < NCH) {
            uint32_t* As = sm + ((c + 1) & 1) * 2 * STAGE;
            uint32_t* Ws = As + STAGE;
            int k0 = (c + 1) * KC;
            #pragma unroll
            for (int v = 0; v < 4; v++) {
                int c4 = lc + v * 4;
                cp16(&As[lr * LDT + c4], Ap + (size_t)lr * Dq + k0 + c4);
                cp16(&Ws[lr * LDT + c4], Wp + (size_t)lr * Dq + k0 + c4);
            }
            cp_commit();
            cp_wait1();
        } else {
            cp_wait0();
        }
        __syncthreads();
        uint32_t* As = sm + cur * 2 * STAGE;
        uint32_t* Ws = As + STAGE;
        #pragma unroll
        for (int ks = 0; ks < KC / 8; ks++) {
            int k8 = ks * 8;
            uint32_t afr[2][4];
            #pragma unroll
            for (int mi = 0; mi < 2; mi++) {
                int rb = wm + mi * 16;
                afr[mi][0] = As[(rb + gid) * LDT + k8 + lig];
                afr[mi][1] = As[(rb + 8 + gid) * LDT + k8 + lig];
                afr[mi][2] = As[(rb + gid) * LDT + k8 + 4 + lig];
                afr[mi][3] = As[(rb + 8 + gid) * LDT + k8 + 4 + lig];
            }
            #pragma unroll
            for (int ni = 0; ni < 8; ni++) {
                uint32_t bfr[2];
                int nb = wn + ni * 8;
                bfr[0] = Ws[(nb + gid) * LDT + k8 + lig];
                bfr[1] = Ws[(nb + gid) * LDT + k8 + 4 + lig];
                mma_tf32(acc[0][ni], afr[0], bfr);
                mma_tf32(acc[1][ni], afr[1], bfr);
            }
        }
        __syncthreads();
    }

    #pragma unroll
    for (int mi = 0; mi < 2; mi++) {
        int rbase = m0 + wm + mi * 16 + gid;
        #pragma unroll
        for (int ni = 0; ni < 8; ni++) {
            int col = n0 + wn + ni * 8 + 2 * lig;
            float bb0 = bias[col], bb1 = bias[col + 1];
            float* p0 = C + (size_t)rbase * Dq + col;
            float* p1 = C + (size_t)(rbase + 8) * Dq + col;
            float2 o0 = {acc[mi][ni][0] + bb0, acc[mi][ni][1] + bb1};
            float2 o1 = {acc[mi][ni][2] + bb0, acc[mi][ni][3] + bb1};
            *(float2*)p0 = o0;
            *(float2*)p1 = o1;
        }
    }
}

// ---------------------------------------------------------------------------
// Fused attention via tf32 mma.sync.
// CTA = (32 q rows) x (one b,h). K loop over 512 in chunks of 128.
// Phase 1: S = QK^T/8 + bias  (mma)  -> smem S[32][516]
// Phase 2: softmax rows, write att (global) + normalized S (smem)
// Phase 3: O = S @ V (mma, accumulate over 4 V chunks) -> g_o
// ---------------------------------------------------------------------------
#define SLD 516
#define CH 128
#define KVLD 68

#define AOFF_KV  (32 * SLD)                 // 16512
#define AOFF_PXK (AOFF_KV + CH * KVLD)      // 25216
#define AOFF_PYK (AOFF_PXK + 512)
#define AOFF_BT  (AOFF_PYK + 512)
#define ATT2_SMEM ((AOFF_BT + 201 + 3) * 4) // ~105.8 KB

__global__ void __launch_bounds__(256, 1) attn_mma(const float* __restrict__ dist_emb,
                                                   float* __restrict__ att) {
    float* sm = (float*)dynsm;
    float* S   = sm;
    float* KV  = sm + AOFF_KV;
    float* pxk = sm + AOFF_PXK;
    float* pyk = sm + AOFF_PYK;
    float* bt  = sm + AOFF_BT;

    int bh = blockIdx.y;
    int b = bh / Hq, h = bh - b * Hq;
    int q0 = blockIdx.x * 32;
    int tid = threadIdx.x;
    int wid = tid >> 5, lane = tid & 31;
    int gid = lane >> 2, lig = lane & 3;

    for (int i = tid; i < Nq; i += 256) {
        pxk[i] = g_px[b * Nq + i];
        pyk[i] = g_py[b * Nq + i];
    }
    for (int i = tid; i < 201; i += 256)
        bt[i] = dist_emb[g_btab[i] * Hq + h];

    // per-thread q-row px/py (rows: gid, gid+8, gid+16, gid+24 -> idx i*2+half)
    float pxr[4], pyr[4];
    #pragma unroll
    for (int i = 0; i < 2; i++)
        #pragma unroll
        for (int half = 0; half < 2; half++) {
            int row = i * 16 + half * 8 + gid;
            pxr[i * 2 + half] = g_px[b * Nq + q0 + row];
            pyr[i * 2 + half] = g_py[b * Nq + q0 + row];
        }

    // Q fragments (A), tf32-rounded, held in registers for all of phase 1
    uint32_t afr[2][8][4];
    #pragma unroll
    for (int i = 0; i < 2; i++) {
        const float* qp  = g_q + ((size_t)((b * Nq + q0 + i * 16 + gid) * Hq + h)) * DKq;
        const float* qp8 = g_q + ((size_t)((b * Nq + q0 + i * 16 + 8 + gid) * Hq + h)) * DKq;
        #pragma unroll
        for (int s = 0; s < 8; s++) {
            afr[i][s][0] = f2tf32u(qp[s * 8 + lig]);
            afr[i][s][1] = f2tf32u(qp8[s * 8 + lig]);
            afr[i][s][2] = f2tf32u(qp[s * 8 + 4 + lig]);
            afr[i][s][3] = f2tf32u(qp8[s * 8 + 4 + lig]);
        }
    }

    // ---- Phase 1: QK^T ----
    for (int c = 0; c < 4; c++) {
        __syncthreads();
        // K chunk -> smem (tf32-rounded): rows kseq-local, cols d
        for (int i = tid; i < CH * 16; i += 256) {
            int r = i >> 4, col = (i & 15) * 4;
            float4 v = *(const float4*)(g_k + ((size_t)((b * Nq + c * CH + r) * Hq + h)) * DKq + col);
            float4 w;
            w.x = f2tf32f(v.x); w.y = f2tf32f(v.y); w.z = f2tf32f(v.z); w.w = f2tf32f(v.w);
            *(float4*)&KV[r * KVLD + col] = w;
        }
        __syncthreads();

        float acc[2][2][4] = {};
        #pragma unroll
        for (int s = 0; s < 8; s++) {
            #pragma unroll
            for (int j = 0; j < 2; j++) {
                uint32_t bfr[2];
                int nrow = 16 * wid + 8 * j + gid;
                bfr[0] = __float_as_uint(KV[nrow * KVLD + s * 8 + lig]);
                bfr[1] = __float_as_uint(KV[nrow * KVLD + s * 8 + 4 + lig]);
                mma_tf32(acc[0][j], afr[0][s], bfr);
                mma_tf32(acc[1][j], afr[1][s], bfr);
            }
        }
        // bias + store to S
        #pragma unroll
        for (int i = 0; i < 2; i++)
            #pragma unroll
            for (int j = 0; j < 2; j++)
                #pragma unroll
                for (int idx = 0; idx < 4; idx++) {
                    int half = idx >> 1;
                    int row = i * 16 + half * 8 + gid;
                    int ks = c * CH + 16 * wid + 8 * j + 2 * lig + (idx & 1);
                    float dx = pxk[ks] - pxr[i * 2 + half];
                    float dy = pyk[ks] - pyr[i * 2 + half];
                    int d2 = (int)(dx * dx + dy * dy);
                    S[row * SLD + ks] = acc[i][j][idx] * 0.125f + bt[d2];
                }
    }
    __syncthreads();

    // ---- Phase 2: softmax (warp w -> rows 4w..4w+3), write att + S ----
    #pragma unroll
    for (int rr = 0; rr < 4; rr++) {
        int q = wid * 4 + rr;
        float vals[16];
        float m = -1e30f;
        #pragma unroll
        for (int j = 0; j < 16; j++) {
            vals[j] = S[q * SLD + lane + j * 32];
            m = fmaxf(m, vals[j]);
        }
        #pragma unroll
        for (int o = 16; o > 0; o >>= 1) m = fmaxf(m, __shfl_xor_sync(0xffffffffu, m, o));
        float s = 0.f;
        #pragma unroll
        for (int j = 0; j < 16; j++) {
            vals[j] = __expf(vals[j] - m);
            s += vals[j];
        }
        #pragma unroll
        for (int o = 16; o > 0; o >>= 1) s += __shfl_xor_sync(0xffffffffu, s, o);
        float inv = 1.0f / s;
        float* arow = att + (((size_t)bh) * Nq + q0 + q) * Nq;
        #pragma unroll
        for (int j = 0; j < 16; j++) {
            float v = vals[j] * inv;
            S[q * SLD + lane + j * 32] = v;
            arow[lane + j * 32] = v;
        }
    }

    // ---- Phase 3: O = S @ V ----
    int mi = wid & 1;
    int nj0 = (wid >> 1) * 2;     // n8 pair {nj0, nj0+1}
    float av[2][4] = {};
    for (int c = 0; c < 4; c++) {
        __syncthreads();
        for (int i = tid; i < CH * 16; i += 256) {
            int r = i >> 4, col = (i & 15) * 4;
            float4 v = *(const float4*)(g_v + ((size_t)((b * Nq + c * CH + r) * Hq + h)) * DKq + col);
            float4 w;
            w.x = f2tf32f(v.x); w.y = f2tf32f(v.y); w.z = f2tf32f(v.z); w.w = f2tf32f(v.w);
            *(float4*)&KV[r * KVLD + col] = w;
        }
        __syncthreads();
        #pragma unroll
        for (int s = 0; s < 16; s++) {
            uint32_t a[4];
            int rbase = (mi * 16 + gid) * SLD + c * CH + s * 8;
            a[0] = f2tf32u(S[rbase + lig]);
            a[1] = f2tf32u(S[rbase + 8 * SLD + lig]);
            a[2] = f2tf32u(S[rbase + 4 + lig]);
            a[3] = f2tf32u(S[rbase + 8 * SLD + 4 + lig]);
            #pragma unroll
            for (int jj = 0; jj < 2; jj++) {
                int n8 = nj0 + jj;
                uint32_t bfr[2];
                bfr[0] = __float_as_uint(KV[(s * 8 + lig) * KVLD + n8 * 8 + gid]);
                bfr[1] = __float_as_uint(KV[(s * 8 + 4 + lig) * KVLD + n8 * 8 + gid]);
                mma_tf32(av[jj], a, bfr);
            }
        }
    }
    #pragma unroll
    for (int jj = 0; jj < 2; jj++)
        #pragma unroll
        for (int half = 0; half < 2; half++) {
            int row = q0 + mi * 16 + half * 8 + gid;
            int col = (nj0 + jj) * 8 + 2 * lig;
            float2 v;
            v.x = f2tf32f(av[jj][half * 2]);
            v.y = f2tf32f(av[jj][half * 2 + 1]);
            *(float2*)(g_o + ((size_t)((b * Nq + row) * Hq + h)) * DKq + col) = v;
        }
}

// ---------------------------------------------------------------------------
// LayerNorm -> tf32-rounded g_x
// ---------------------------------------------------------------------------
__global__ void __launch_bounds__(256) ln_kernel(const float* __restrict__ f,
                                                 const float* __restrict__ gamma,
                                                 const float* __restrict__ beta) {
    int t = blockIdx.x;
    const float* in = f + (size_t)t * Dq;
    float* out = g_x + (size_t)t * Dq;
    int tid = threadIdx.x;
    float v0 = in[tid], v1 = in[tid + 256], v2 = in[tid + 512];

    __shared__ float red[8];
    __shared__ float bc;

    float s = v0 + v1 + v2;
    #pragma unroll
    for (int o = 16; o > 0; o >>= 1) s += __shfl_down_sync(0xffffffffu, s, o);
    if ((tid & 31) == 0) red[tid >> 5] = s;
    __syncthreads();
    if (tid == 0) {
        float tot = 0.f;
        #pragma unroll
        for (int i = 0; i < 8; i++) tot += red[i];
        bc = tot * (1.0f / 768.0f);
    }
    __syncthreads();
    float mean = bc;
    float d0 = v0 - mean, d1 = v1 - mean, d2 = v2 - mean;
    float ss = d0 * d0 + d1 * d1 + d2 * d2;
    #pragma unroll
    for (int o = 16; o > 0; o >>= 1) ss += __shfl_down_sync(0xffffffffu, ss, o);
    __syncthreads();
    if ((tid & 31) == 0) red[tid >> 5] = ss;
    __syncthreads();
    if (tid == 0) {
        float tot = 0.f;
        #pragma unroll
        for (int i = 0; i < 8; i++) tot += red[i];
        bc = tot * (1.0f / 768.0f);
    }
    __syncthreads();
    float inv = rsqrtf(bc + 1e-5f);
    out[tid]       = f2tf32f(d0 * inv * gamma[tid]       + beta[tid]);
    out[tid + 256] = f2tf32f(d1 * inv * gamma[tid + 256] + beta[tid + 256]);
    out[tid + 512] = f2tf32f(d2 * inv * gamma[tid + 512] + beta[tid + 512]);
}

// ---------------------------------------------------------------------------
// Convert 4 weight matrices to tf32-rounded copies
// ---------------------------------------------------------------------------
__global__ void __launch_bounds__(256) cvtw_kernel(const float* __restrict__ Wq,
                                                   const float* __restrict__ Wk,
                                                   const float* __restrict__ Wv,
                                                   const float* __restrict__ Wo) {
    int i = blockIdx.x * 256 + threadIdx.x;
    if (i >= Dq * Dq) return;
    g_wq[i] = f2tf32f(Wq[i]);
    g_wk[i] = f2tf32f(Wk[i]);
    g_wv[i] = f2tf32f(Wv[i]);
    g_wo[i] = f2tf32f(Wo[i]);
}

// ---------------------------------------------------------------------------
// Patch bins
// ---------------------------------------------------------------------------
__global__ void __launch_bounds__(256) bins_kernel(const float* __restrict__ boxes,
                                                   const int* __restrict__ im) {
    int idx = blockIdx.x * blockDim.x + threadIdx.x;
    if (idx < 201) g_btab[idx] = (int)(2.0 * sqrt((double)idx));
    if (idx >= TOK) return;
    int b = idx / Nq;
    float wf = (float)im[b * 4 + 0];
    float hf = (float)im[b * 4 + 1];
    const float* bx = boxes + (size_t)idx * 4;
    float x1 = bx[0] * wf, y1 = bx[1] * hf, x2 = bx[2] * wf, y2 = bx[3] * hf;
    float spw = floorf(wf / 11.0f), sph = floorf(hf / 11.0f);
    float cx = floorf((x1 + x2) / 2.0f), cy = floorf((y1 + y2) / 2.0f);
    int px = 0, py = 0;
    #pragma unroll
    for (int i = 0; i < 11; i++) {
        float lo = (float)i * spw, hi = (float)(i + 1) * spw;
        if (lo <= cx && cx <= hi) { px = i; break; }
    }
    #pragma unroll
    for (int i = 0; i < 11; i++) {
        float lo = (float)i * sph, hi = (float)(i + 1) * sph;
        if (lo <= cy && cy <= hi) { py = i; break; }
    }
    g_px[idx] = (float)px;
    g_py[idx] = (float)py;
}

// ---------------------------------------------------------------------------
extern "C" void kernel_launch(void* const* d_in, const int* in_sizes, int n_in,
                              void* d_out, int out_size) {
    const float* features = (const float*)d_in[0];
    const float* boxes    = (const float*)d_in[1];
    const int*   im       = (const int*)d_in[2];
    const float* Wq = (const float*)d_in[3];  const float* bqv = (const float*)d_in[4];
    const float* Wk = (const float*)d_in[5];  const float* bkv = (const float*)d_in[6];
    const float* Wv = (const float*)d_in[7];  const float* bvv = (const float*)d_in[8];
    const float* Wo = (const float*)d_in[9];  const float* bov = (const float*)d_in[10];
    const float* gamma = (const float*)d_in[11];
    const float* beta  = (const float*)d_in[12];
    const float* demb  = (const float*)d_in[13];

    float* out = (float*)d_out;
    float* att = out + (size_t)TOK * Dq;

    void *px_, *pq_, *pk_, *pv_, *po_, *pwq_, *pwk_, *pwv_, *pwo_;
    cudaGetSymbolAddress(&px_, g_x);
    cudaGetSymbolAddress(&pq_, g_q);
    cudaGetSymbolAddress(&pk_, g_k);
    cudaGetSymbolAddress(&pv_, g_v);
    cudaGetSymbolAddress(&po_, g_o);
    cudaGetSymbolAddress(&pwq_, g_wq);
    cudaGetSymbolAddress(&pwk_, g_wk);
    cudaGetSymbolAddress(&pwv_, g_wv);
    cudaGetSymbolAddress(&pwo_, g_wo);

    const int GEMM_SMEM = 4 * STAGE * 4;   // 81920 B
    cudaFuncSetAttribute(hmma_gemm, cudaFuncAttributeMaxDynamicSharedMemorySize, GEMM_SMEM);
    cudaFuncSetAttribute(attn_mma, cudaFuncAttributeMaxDynamicSharedMemorySize, ATT2_SMEM);

    ln_kernel<<<TOK, 256>>>(features, gamma, beta);
    bins_kernel<<<(TOK + 255) / 256, 256>>>(boxes, im);
    cvtw_kernel<<<(Dq * Dq + 255) / 256, 256>>>(Wq, Wk, Wv, Wo);

    // QKV projections in one launch
    dim3 gqkv(Dq / 128, TOK / 128, 3);
    hmma_gemm<<<gqkv, 256, GEMM_SMEM>>>(
        (const float*)px_,
        (const float*)pwq_, bqv, (float*)pq_,
        (const float*)pwk_, bkv, (float*)pk_,
        (const float*)pwv_, bvv, (float*)pv_);

    // Fused tensor-core attention
    attn_mma<<<dim3(Nq / 32, Bq * Hq), 256, ATT2_SMEM>>>(demb, att);

    // Output projection
    dim3 gout(Dq / 128, TOK / 128, 1);
    hmma_gemm<<<gout, 256, GEMM_SMEM>>>(
        (const float*)po_,
        (const float*)pwo_, bov, out,
        (const float*)pwo_, bov, out,
        (const float*)pwo_, bov, out);
}

// round 10
// speedup vs baseline: 2.4605x; 1.2365x over previous
#include <cuda_runtime.h>
#include <math.h>
#include <stdint.h>

#define Bq 16
#define Nq 512
#define Dq 768
#define Hq 12
#define DKq 64
#define TOK (Bq*Nq)   // 8192

// Scratch
__device__ float g_x[TOK*Dq];        // layernormed, tf32-rounded
__device__ float g_q[TOK*Dq];        // (B,N,H,DK) tf32-rounded
__device__ float g_k[TOK*Dq];        // tf32-rounded
__device__ float g_v[TOK*Dq];        // tf32-rounded
__device__ float g_o[TOK*Dq];        // attention out, tf32-rounded
__device__ float g_wq[Dq*Dq];        // tf32-rounded weights
__device__ float g_wk[Dq*Dq];
__device__ float g_wv[Dq*Dq];
__device__ float g_wo[Dq*Dq];
__device__ float g_px[TOK];
__device__ float g_py[TOK];
__device__ int   g_btab[201];

// single dynamic shared buffer shared across kernels
extern __shared__ uint4 dynsm[];

// ---------------------------------------------------------------------------
// helpers
// ---------------------------------------------------------------------------
__device__ __forceinline__ float f2tf32f(float f) {
    uint32_t u;
    asm("cvt.rna.tf32.f32 %0, %1;" : "=r"(u) : "f"(f));
    return __uint_as_float(u);
}
__device__ __forceinline__ void mma_tf32(float c[4], const uint32_t a[4], const uint32_t b[2]) {
    asm volatile(
        "mma.sync.aligned.m16n8k8.row.col.f32.tf32.tf32.f32 "
        "{%0,%1,%2,%3}, {%4,%5,%6,%7}, {%8,%9}, {%0,%1,%2,%3};"
        : "+f"(c[0]), "+f"(c[1]), "+f"(c[2]), "+f"(c[3])
        : "r"(a[0]), "r"(a[1]), "r"(a[2]), "r"(a[3]), "r"(b[0]), "r"(b[1]));
}
__device__ __forceinline__ void cp16(void* smem, const void* g) {
    uint32_t sa = (uint32_t)__cvta_generic_to_shared(smem);
    asm volatile("cp.async.ca.shared.global [%0], [%1], 16;" :: "r"(sa), "l"(g));
}
__device__ __forceinline__ void cp_commit() {
    asm volatile("cp.async.commit_group;" ::: "memory");
}
__device__ __forceinline__ void cp_wait1() {
    asm volatile("cp.async.wait_group 1;" ::: "memory");
}
__device__ __forceinline__ void cp_wait0() {
    asm volatile("cp.async.wait_group 0;" ::: "memory");
}

// ---------------------------------------------------------------------------
// tf32 mma.sync GEMM: C = A @ W^T + bias (+optional tf32 rounding of C)
// CTA tile 128x128, KC=32, cp.async double buffer. grid.z selects W/bias/C.
// ---------------------------------------------------------------------------
#define KC 32
#define LDT 40
#define STAGE (128 * LDT)   // uint32s per matrix per stage

__global__ void __launch_bounds__(256) hmma_gemm(const float* __restrict__ A0,
                                                 const float* __restrict__ W0,
                                                 const float* __restrict__ b0,
                                                 float* __restrict__ C0,
                                                 const float* __restrict__ W1,
                                                 const float* __restrict__ b1,
                                                 float* __restrict__ C1,
                                                 const float* __restrict__ W2,
                                                 const float* __restrict__ b2,
                                                 float* __restrict__ C2,
                                                 int round_c) {
    uint32_t* sm = (uint32_t*)dynsm;
    int z = blockIdx.z;
    const float* A = A0;
    const float* W = (z == 0) ? W0 : (z == 1) ? W1 : W2;
    const float* bias = (z == 0) ? b0 : (z == 1) ? b1 : b2;
    float* C = (z == 0) ? C0 : (z == 1) ? C1 : C2;

    int tid = threadIdx.x;
    int wid = tid >> 5, lane = tid & 31;
    int wm = (wid >> 1) * 32;
    int wn = (wid & 1) * 64;
    int gid = lane >> 2;
    int lig = lane & 3;
    int m0 = blockIdx.y * 128, n0 = blockIdx.x * 128;

    const float* Ap = A + (size_t)m0 * Dq;
    const float* Wp = W + (size_t)n0 * Dq;

    int lr = tid >> 1;
    int lc = (tid & 1) * 16;

    float acc[2][8][4];
    #pragma unroll
    for (int mi = 0; mi < 2; mi++)
        #pragma unroll
        for (int ni = 0; ni < 8; ni++)
            #pragma unroll
            for (int j = 0; j < 4; j++) acc[mi][ni][j] = 0.f;

    {
        uint32_t* As = sm;
        uint32_t* Ws = sm + STAGE;
        #pragma unroll
        for (int v = 0; v < 4; v++) {
            int c4 = lc + v * 4;
            cp16(&As[lr * LDT + c4], Ap + (size_t)lr * Dq + c4);
            cp16(&Ws[lr * LDT + c4], Wp + (size_t)lr * Dq + c4);
        }
        cp_commit();
    }

    const int NCH = Dq / KC;  // 24
    for (int c = 0; c < NCH; c++) {
        int cur = c & 1;
        if (c + 1 < NCH) {
            uint32_t* As = sm + ((c + 1) & 1) * 2 * STAGE;
            uint32_t* Ws = As + STAGE;
            int k0 = (c + 1) * KC;
            #pragma unroll
            for (int v = 0; v < 4; v++) {
                int c4 = lc + v * 4;
                cp16(&As[lr * LDT + c4], Ap + (size_t)lr * Dq + k0 + c4);
                cp16(&Ws[lr * LDT + c4], Wp + (size_t)lr * Dq + k0 + c4);
            }
            cp_commit();
            cp_wait1();
        } else {
            cp_wait0();
        }
        __syncthreads();
        uint32_t* As = sm + cur * 2 * STAGE;
        uint32_t* Ws = As + STAGE;
        #pragma unroll
        for (int ks = 0; ks < KC / 8; ks++) {
            int k8 = ks * 8;
            uint32_t afr[2][4];
            #pragma unroll
            for (int mi = 0; mi < 2; mi++) {
                int rb = wm + mi * 16;
                afr[mi][0] = As[(rb + gid) * LDT + k8 + lig];
                afr[mi][1] = As[(rb + 8 + gid) * LDT + k8 + lig];
                afr[mi][2] = As[(rb + gid) * LDT + k8 + 4 + lig];
                afr[mi][3] = As[(rb + 8 + gid) * LDT + k8 + 4 + lig];
            }
            #pragma unroll
            for (int ni = 0; ni < 8; ni++) {
                uint32_t bfr[2];
                int nb = wn + ni * 8;
                bfr[0] = Ws[(nb + gid) * LDT + k8 + lig];
                bfr[1] = Ws[(nb + gid) * LDT + k8 + 4 + lig];
                mma_tf32(acc[0][ni], afr[0], bfr);
                mma_tf32(acc[1][ni], afr[1], bfr);
            }
        }
        __syncthreads();
    }

    #pragma unroll
    for (int mi = 0; mi < 2; mi++) {
        int rbase = m0 + wm + mi * 16 + gid;
        #pragma unroll
        for (int ni = 0; ni < 8; ni++) {
            int col = n0 + wn + ni * 8 + 2 * lig;
            float bb0 = bias[col], bb1 = bias[col + 1];
            float* p0 = C + (size_t)rbase * Dq + col;
            float* p1 = C + (size_t)(rbase + 8) * Dq + col;
            float2 o0 = {acc[mi][ni][0] + bb0, acc[mi][ni][1] + bb1};
            float2 o1 = {acc[mi][ni][2] + bb0, acc[mi][ni][3] + bb1};
            if (round_c) {
                o0.x = f2tf32f(o0.x); o0.y = f2tf32f(o0.y);
                o1.x = f2tf32f(o1.x); o1.y = f2tf32f(o1.y);
            }
            *(float2*)p0 = o0;
            *(float2*)p1 = o1;
        }
    }
}

// ---------------------------------------------------------------------------
// Fused attention via tf32 mma.sync, cp.async double-buffered K/V (CH=64).
// Operands (g_q/g_k/g_v) already tf32-rounded by the projection epilogue.
// Phase 1: S = QK^T/8 + bias (mma) -> smem S[32][516] (fp32)
// Phase 2: softmax rows, write att (fp32) + tf32-rounded S
// Phase 3: O = S @ V (mma) -> g_o (tf32-rounded)
// ---------------------------------------------------------------------------
#define SLD 516
#define CH 64
#define KVLD 68
#define KVBUF (CH * KVLD)                   // 4352 floats

#define AOFF_KV  (32 * SLD)                 // 16512
#define AOFF_PXK (AOFF_KV + 2 * KVBUF)      // 25216
#define AOFF_PYK (AOFF_PXK + 512)
#define AOFF_BT  (AOFF_PYK + 512)
#define ATT2_SMEM ((AOFF_BT + 201 + 3) * 4) // ~105.8 KB

__device__ __forceinline__ void ldchunk(float* dst, const float* src, int tid) {
    // copy 64 rows x 64 floats (row stride Hq*DKq in global, KVLD in smem)
    #pragma unroll
    for (int i = 0; i < 4; i++) {
        int idx = tid + i * 256;           // 0..1023 segments of 16B
        int r = idx >> 4, c4 = (idx & 15) * 4;
        cp16(&dst[r * KVLD + c4], src + (size_t)r * (Hq * DKq) + c4);
    }
}

__global__ void __launch_bounds__(256) attn_mma(const float* __restrict__ dist_emb,
                                                float* __restrict__ att) {
    float* sm = (float*)dynsm;
    float* S   = sm;
    float* KV0 = sm + AOFF_KV;
    float* KV1 = KV0 + KVBUF;
    float* pxk = sm + AOFF_PXK;
    float* pyk = sm + AOFF_PYK;
    float* bt  = sm + AOFF_BT;

    int bh = blockIdx.y;
    int b = bh / Hq, h = bh - b * Hq;
    int q0 = blockIdx.x * 32;
    int tid = threadIdx.x;
    int wid = tid >> 5, lane = tid & 31;
    int gid = lane >> 2, lig = lane & 3;

    const float* kbase = g_k + ((size_t)(b * Nq) * Hq + h) * DKq;
    const float* vbase = g_v + ((size_t)(b * Nq) * Hq + h) * DKq;

    // prefetch K chunk 0
    ldchunk(KV0, kbase, tid);
    cp_commit();

    for (int i = tid; i < Nq; i += 256) {
        pxk[i] = g_px[b * Nq + i];
        pyk[i] = g_py[b * Nq + i];
    }
    for (int i = tid; i < 201; i += 256)
        bt[i] = dist_emb[g_btab[i] * Hq + h];

    // per-thread q-row px/py (row = i*16 + half*8 + gid)
    float pxr[4], pyr[4];
    #pragma unroll
    for (int i = 0; i < 2; i++)
        #pragma unroll
        for (int half = 0; half < 2; half++) {
            int row = i * 16 + half * 8 + gid;
            pxr[i * 2 + half] = g_px[b * Nq + q0 + row];
            pyr[i * 2 + half] = g_py[b * Nq + q0 + row];
        }

    // Q fragments (already tf32-rounded in memory)
    uint32_t afr[2][8][4];
    #pragma unroll
    for (int i = 0; i < 2; i++) {
        const float* qp  = g_q + ((size_t)((b * Nq + q0 + i * 16 + gid) * Hq + h)) * DKq;
        const float* qp8 = g_q + ((size_t)((b * Nq + q0 + i * 16 + 8 + gid) * Hq + h)) * DKq;
        #pragma unroll
        for (int s = 0; s < 8; s++) {
            afr[i][s][0] = __float_as_uint(qp[s * 8 + lig]);
            afr[i][s][1] = __float_as_uint(qp8[s * 8 + lig]);
            afr[i][s][2] = __float_as_uint(qp[s * 8 + 4 + lig]);
            afr[i][s][3] = __float_as_uint(qp8[s * 8 + 4 + lig]);
        }
    }

    // ---- Phase 1: QK^T, 8 chunks of 64 k-seq, double buffered ----
    for (int c = 0; c < 8; c++) {
        cp_wait0();
        __syncthreads();
        if (c < 8 - 1) {
            ldchunk((c & 1) ? KV0 : KV1, kbase + (size_t)(c + 1) * CH * Hq * DKq, tid);
            cp_commit();
        }
        const float* KV = (c & 1) ? KV1 : KV0;

        float acc[2][4] = {};
        #pragma unroll
        for (int s = 0; s < 8; s++) {
            uint32_t bfr[2];
            int nrow = 8 * wid + gid;
            bfr[0] = __float_as_uint(KV[nrow * KVLD + s * 8 + lig]);
            bfr[1] = __float_as_uint(KV[nrow * KVLD + s * 8 + 4 + lig]);
            mma_tf32(acc[0], afr[0][s], bfr);
            mma_tf32(acc[1], afr[1][s], bfr);
        }
        // bias + store to S (fp32)
        #pragma unroll
        for (int i = 0; i < 2; i++)
            #pragma unroll
            for (int idx = 0; idx < 4; idx++) {
                int half = idx >> 1;
                int row = i * 16 + half * 8 + gid;
                int ks = c * CH + 8 * wid + 2 * lig + (idx & 1);
                float dx = pxk[ks] - pxr[i * 2 + half];
                float dy = pyk[ks] - pyr[i * 2 + half];
                int d2 = (int)(dx * dx + dy * dy);
                S[row * SLD + ks] = acc[i][idx] * 0.125f + bt[d2];
            }
    }

    // prefetch V chunk 0 into KV0 (safe: all warps done with K chunk 6 after
    // the sync at top of c=7; chunk 7 lives in KV1)
    ldchunk(KV0, vbase, tid);
    cp_commit();
    __syncthreads();   // S complete for softmax

    // ---- Phase 2: softmax (warp w -> rows 4w..4w+3), att fp32, S tf32 ----
    #pragma unroll
    for (int rr = 0; rr < 4; rr++) {
        int q = wid * 4 + rr;
        float vals[16];
        float m = -1e30f;
        #pragma unroll
        for (int j = 0; j < 16; j++) {
            vals[j] = S[q * SLD + lane + j * 32];
            m = fmaxf(m, vals[j]);
        }
        #pragma unroll
        for (int o = 16; o > 0; o >>= 1) m = fmaxf(m, __shfl_xor_sync(0xffffffffu, m, o));
        float s = 0.f;
        #pragma unroll
        for (int j = 0; j < 16; j++) {
            vals[j] = __expf(vals[j] - m);
            s += vals[j];
        }
        #pragma unroll
        for (int o = 16; o > 0; o >>= 1) s += __shfl_xor_sync(0xffffffffu, s, o);
        float inv = 1.0f / s;
        float* arow = att + (((size_t)bh) * Nq + q0 + q) * Nq;
        #pragma unroll
        for (int j = 0; j < 16; j++) {
            float v = vals[j] * inv;
            S[q * SLD + lane + j * 32] = f2tf32f(v);
            arow[lane + j * 32] = v;
        }
    }

    // ---- Phase 3: O = S @ V, double buffered ----
    int mi = wid & 1;
    int nj0 = (wid >> 1) * 2;     // n8 pair {nj0, nj0+1}
    float av[2][4] = {};
    for (int c = 0; c < 8; c++) {
        cp_wait0();
        __syncthreads();
        if (c < 8 - 1) {
            ldchunk((c & 1) ? KV0 : KV1, vbase + (size_t)(c + 1) * CH * Hq * DKq, tid);
            cp_commit();
        }
        const float* KV = (c & 1) ? KV1 : KV0;
        #pragma unroll
        for (int s = 0; s < 8; s++) {
            uint32_t a[4];
            int rbase = (mi * 16 + gid) * SLD + c * CH + s * 8;
            a[0] = __float_as_uint(S[rbase + lig]);
            a[1] = __float_as_uint(S[rbase + 8 * SLD + lig]);
            a[2] = __float_as_uint(S[rbase + 4 + lig]);
            a[3] = __float_as_uint(S[rbase + 8 * SLD + 4 + lig]);
            #pragma unroll
            for (int jj = 0; jj < 2; jj++) {
                int n8 = nj0 + jj;
                uint32_t bfr[2];
                bfr[0] = __float_as_uint(KV[(s * 8 + lig) * KVLD + n8 * 8 + gid]);
                bfr[1] = __float_as_uint(KV[(s * 8 + 4 + lig) * KVLD + n8 * 8 + gid]);
                mma_tf32(av[jj], a, bfr);
            }
        }
    }
    #pragma unroll
    for (int jj = 0; jj < 2; jj++)
        #pragma unroll
        for (int half = 0; half < 2; half++) {
            int row = q0 + mi * 16 + half * 8 + gid;
            int col = (nj0 + jj) * 8 + 2 * lig;
            float2 v;
            v.x = f2tf32f(av[jj][half * 2]);
            v.y = f2tf32f(av[jj][half * 2 + 1]);
            *(float2*)(g_o + ((size_t)((b * Nq + row) * Hq + h)) * DKq + col) = v;
        }
}

// ---------------------------------------------------------------------------
// LayerNorm -> tf32-rounded g_x
// ---------------------------------------------------------------------------
__global__ void __launch_bounds__(256) ln_kernel(const float* __restrict__ f,
                                                 const float* __restrict__ gamma,
                                                 const float* __restrict__ beta) {
    int t = blockIdx.x;
    const float* in = f + (size_t)t * Dq;
    float* out = g_x + (size_t)t * Dq;
    int tid = threadIdx.x;
    float v0 = in[tid], v1 = in[tid + 256], v2 = in[tid + 512];

    __shared__ float red[8];
    __shared__ float bc;

    float s = v0 + v1 + v2;
    #pragma unroll
    for (int o = 16; o > 0; o >>= 1) s += __shfl_down_sync(0xffffffffu, s, o);
    if ((tid & 31) == 0) red[tid >> 5] = s;
    __syncthreads();
    if (tid == 0) {
        float tot = 0.f;
        #pragma unroll
        for (int i = 0; i < 8; i++) tot += red[i];
        bc = tot * (1.0f / 768.0f);
    }
    __syncthreads();
    float mean = bc;
    float d0 = v0 - mean, d1 = v1 - mean, d2 = v2 - mean;
    float ss = d0 * d0 + d1 * d1 + d2 * d2;
    #pragma unroll
    for (int o = 16; o > 0; o >>= 1) ss += __shfl_down_sync(0xffffffffu, ss, o);
    __syncthreads();
    if ((tid & 31) == 0) red[tid >> 5] = ss;
    __syncthreads();
    if (tid == 0) {
        float tot = 0.f;
        #pragma unroll
        for (int i = 0; i < 8; i++) tot += red[i];
        bc = tot * (1.0f / 768.0f);
    }
    __syncthreads();
    float inv = rsqrtf(bc + 1e-5f);
    out[tid]       = f2tf32f(d0 * inv * gamma[tid]       + beta[tid]);
    out[tid + 256] = f2tf32f(d1 * inv * gamma[tid + 256] + beta[tid + 256]);
    out[tid + 512] = f2tf32f(d2 * inv * gamma[tid + 512] + beta[tid + 512]);
}

// ---------------------------------------------------------------------------
// Convert 4 weight matrices to tf32-rounded copies
// ---------------------------------------------------------------------------
__global__ void __launch_bounds__(256) cvtw_kernel(const float* __restrict__ Wq,
                                                   const float* __restrict__ Wk,
                                                   const float* __restrict__ Wv,
                                                   const float* __restrict__ Wo) {
    int i = blockIdx.x * 256 + threadIdx.x;
    if (i >= Dq * Dq) return;
    g_wq[i] = f2tf32f(Wq[i]);
    g_wk[i] = f2tf32f(Wk[i]);
    g_wv[i] = f2tf32f(Wv[i]);
    g_wo[i] = f2tf32f(Wo[i]);
}

// ---------------------------------------------------------------------------
// Patch bins
// ---------------------------------------------------------------------------
__global__ void __launch_bounds__(256) bins_kernel(const float* __restrict__ boxes,
                                                   const int* __restrict__ im) {
    int idx = blockIdx.x * blockDim.x + threadIdx.x;
    if (idx < 201) g_btab[idx] = (int)(2.0 * sqrt((double)idx));
    if (idx >= TOK) return;
    int b = idx / Nq;
    float wf = (float)im[b * 4 + 0];
    float hf = (float)im[b * 4 + 1];
    const float* bx = boxes + (size_t)idx * 4;
    float x1 = bx[0] * wf, y1 = bx[1] * hf, x2 = bx[2] * wf, y2 = bx[3] * hf;
    float spw = floorf(wf / 11.0f), sph = floorf(hf / 11.0f);
    float cx = floorf((x1 + x2) / 2.0f), cy = floorf((y1 + y2) / 2.0f);
    int px = 0, py = 0;
    #pragma unroll
    for (int i = 0; i < 11; i++) {
        float lo = (float)i * spw, hi = (float)(i + 1) * spw;
        if (lo <= cx && cx <= hi) { px = i; break; }
    }
    #pragma unroll
    for (int i = 0; i < 11; i++) {
        float lo = (float)i * sph, hi = (float)(i + 1) * sph;
        if (lo <= cy && cy <= hi) { py = i; break; }
    }
    g_px[idx] = (float)px;
    g_py[idx] = (float)py;
}

// ---------------------------------------------------------------------------
extern "C" void kernel_launch(void* const* d_in, const int* in_sizes, int n_in,
                              void* d_out, int out_size) {
    const float* features = (const float*)d_in[0];
    const float* boxes    = (const float*)d_in[1];
    const int*   im       = (const int*)d_in[2];
    const float* Wq = (const float*)d_in[3];  const float* bqv = (const float*)d_in[4];
    const float* Wk = (const float*)d_in[5];  const float* bkv = (const float*)d_in[6];
    const float* Wv = (const float*)d_in[7];  const float* bvv = (const float*)d_in[8];
    const float* Wo = (const float*)d_in[9];  const float* bov = (const float*)d_in[10];
    const float* gamma = (const float*)d_in[11];
    const float* beta  = (const float*)d_in[12];
    const float* demb  = (const float*)d_in[13];

    float* out = (float*)d_out;
    float* att = out + (size_t)TOK * Dq;

    void *px_, *pq_, *pk_, *pv_, *po_, *pwq_, *pwk_, *pwv_, *pwo_;
    cudaGetSymbolAddress(&px_, g_x);
    cudaGetSymbolAddress(&pq_, g_q);
    cudaGetSymbolAddress(&pk_, g_k);
    cudaGetSymbolAddress(&pv_, g_v);
    cudaGetSymbolAddress(&po_, g_o);
    cudaGetSymbolAddress(&pwq_, g_wq);
    cudaGetSymbolAddress(&pwk_, g_wk);
    cudaGetSymbolAddress(&pwv_, g_wv);
    cudaGetSymbolAddress(&pwo_, g_wo);

    const int GEMM_SMEM = 4 * STAGE * 4;   // 81920 B
    cudaFuncSetAttribute(hmma_gemm, cudaFuncAttributeMaxDynamicSharedMemorySize, GEMM_SMEM);
    cudaFuncSetAttribute(attn_mma, cudaFuncAttributeMaxDynamicSharedMemorySize, ATT2_SMEM);

    ln_kernel<<<TOK, 256>>>(features, gamma, beta);
    bins_kernel<<<(TOK + 255) / 256, 256>>>(boxes, im);
    cvtw_kernel<<<(Dq * Dq + 255) / 256, 256>>>(Wq, Wk, Wv, Wo);

    // QKV projections in one launch; outputs tf32-rounded for attention
    dim3 gqkv(Dq / 128, TOK / 128, 3);
    hmma_gemm<<<gqkv, 256, GEMM_SMEM>>>(
        (const float*)px_,
        (const float*)pwq_, bqv, (float*)pq_,
        (const float*)pwk_, bkv, (float*)pk_,
        (const float*)pwv_, bvv, (float*)pv_, 1);

    // Fused tensor-core attention
    attn_mma<<<dim3(Nq / 32, Bq * Hq), 256, ATT2_SMEM>>>(demb, att);

    // Output projection (NOT rounded — final output)
    dim3 gout(Dq / 128, TOK / 128, 1);
    hmma_gemm<<<gout, 256, GEMM_SMEM>>>(
        (const float*)po_,
        (const float*)pwo_, bov, out,
        (const float*)pwo_, bov, out,
        (const float*)pwo_, bov, out, 0);
}

// round 11
// speedup vs baseline: 2.6071x; 1.0596x over previous
#include <cuda_runtime.h>
#include <math.h>
#include <stdint.h>

#define Bq 16
#define Nq 512
#define Dq 768
#define Hq 12
#define DKq 64
#define TOK (Bq*Nq)   // 8192

// Scratch
__device__ float g_x[TOK*Dq];        // layernormed, tf32-rounded
__device__ float g_q[TOK*Dq];        // (B,N,H,DK) tf32-rounded
__device__ float g_k[TOK*Dq];        // tf32-rounded
__device__ float g_v[TOK*Dq];        // tf32-rounded
__device__ float g_o[TOK*Dq];        // attention out, tf32-rounded
__device__ float g_wq[Dq*Dq];        // tf32-rounded weights
__device__ float g_wk[Dq*Dq];
__device__ float g_wv[Dq*Dq];
__device__ float g_wo[Dq*Dq];
__device__ float g_px[TOK];
__device__ float g_py[TOK];
__device__ int   g_btab[201];

// single dynamic shared buffer shared across kernels
extern __shared__ uint4 dynsm[];

// ---------------------------------------------------------------------------
// helpers
// ---------------------------------------------------------------------------
__device__ __forceinline__ float f2tf32f(float f) {
    uint32_t u;
    asm("cvt.rna.tf32.f32 %0, %1;" : "=r"(u) : "f"(f));
    return __uint_as_float(u);
}
__device__ __forceinline__ void mma_tf32(float c[4], const uint32_t a[4], const uint32_t b[2]) {
    asm volatile(
        "mma.sync.aligned.m16n8k8.row.col.f32.tf32.tf32.f32 "
        "{%0,%1,%2,%3}, {%4,%5,%6,%7}, {%8,%9}, {%0,%1,%2,%3};"
        : "+f"(c[0]), "+f"(c[1]), "+f"(c[2]), "+f"(c[3])
        : "r"(a[0]), "r"(a[1]), "r"(a[2]), "r"(a[3]), "r"(b[0]), "r"(b[1]));
}
__device__ __forceinline__ void cp16(void* smem, const void* g) {
    uint32_t sa = (uint32_t)__cvta_generic_to_shared(smem);
    asm volatile("cp.async.ca.shared.global [%0], [%1], 16;" :: "r"(sa), "l"(g));
}
__device__ __forceinline__ void cp_commit() {
    asm volatile("cp.async.commit_group;" ::: "memory");
}
__device__ __forceinline__ void cp_wait1() {
    asm volatile("cp.async.wait_group 1;" ::: "memory");
}
__device__ __forceinline__ void cp_wait0() {
    asm volatile("cp.async.wait_group 0;" ::: "memory");
}

// ---------------------------------------------------------------------------
// tf32 mma.sync GEMM: C = A @ W^T + bias (+optional tf32 rounding of C)
// CTA tile 128x128, 512 threads, warp grid 4x4 (warp tile 32x32), KC=32,
// cp.async double buffer. grid.z selects W/bias/C.
// ---------------------------------------------------------------------------
#define KC 32
#define LDT 40
#define STAGE (128 * LDT)   // uint32s per matrix per stage

__global__ void __launch_bounds__(512, 2) hmma_gemm(
        const float* __restrict__ A0,
        const float* __restrict__ W0, const float* __restrict__ b0, float* __restrict__ C0,
        const float* __restrict__ W1, const float* __restrict__ b1, float* __restrict__ C1,
        const float* __restrict__ W2, const float* __restrict__ b2, float* __restrict__ C2,
        int round_c) {
    uint32_t* sm = (uint32_t*)dynsm;
    int z = blockIdx.z;
    const float* A = A0;
    const float* W = (z == 0) ? W0 : (z == 1) ? W1 : W2;
    const float* bias = (z == 0) ? b0 : (z == 1) ? b1 : b2;
    float* C = (z == 0) ? C0 : (z == 1) ? C1 : C2;

    int tid = threadIdx.x;
    int wid = tid >> 5, lane = tid & 31;
    int wm = (wid >> 2) * 32;          // 4 warp rows
    int wn = (wid & 3) * 32;           // 4 warp cols
    int gid = lane >> 2;
    int lig = lane & 3;
    int m0 = blockIdx.y * 128, n0 = blockIdx.x * 128;

    const float* Ap = A + (size_t)m0 * Dq;
    const float* Wp = W + (size_t)n0 * Dq;

    // fill mapping: 512 threads, 128 rows x 32 floats per matrix
    int lr = tid >> 2;                 // row 0..127
    int lc = (tid & 3) * 8;            // float col 0,8,16,24 (two cp16 each)

    float acc[2][4][4];
    #pragma unroll
    for (int mi = 0; mi < 2; mi++)
        #pragma unroll
        for (int ni = 0; ni < 4; ni++)
            #pragma unroll
            for (int j = 0; j < 4; j++) acc[mi][ni][j] = 0.f;

    {
        uint32_t* As = sm;
        uint32_t* Ws = sm + STAGE;
        cp16(&As[lr * LDT + lc],     Ap + (size_t)lr * Dq + lc);
        cp16(&As[lr * LDT + lc + 4], Ap + (size_t)lr * Dq + lc + 4);
        cp16(&Ws[lr * LDT + lc],     Wp + (size_t)lr * Dq + lc);
        cp16(&Ws[lr * LDT + lc + 4], Wp + (size_t)lr * Dq + lc + 4);
        cp_commit();
    }

    const int NCH = Dq / KC;  // 24
    for (int c = 0; c < NCH; c++) {
        int cur = c & 1;
        if (c + 1 < NCH) {
            uint32_t* As = sm + ((c + 1) & 1) * 2 * STAGE;
            uint32_t* Ws = As + STAGE;
            int k0 = (c + 1) * KC;
            cp16(&As[lr * LDT + lc],     Ap + (size_t)lr * Dq + k0 + lc);
            cp16(&As[lr * LDT + lc + 4], Ap + (size_t)lr * Dq + k0 + lc + 4);
            cp16(&Ws[lr * LDT + lc],     Wp + (size_t)lr * Dq + k0 + lc);
            cp16(&Ws[lr * LDT + lc + 4], Wp + (size_t)lr * Dq + k0 + lc + 4);
            cp_commit();
            cp_wait1();
        } else {
            cp_wait0();
        }
        __syncthreads();
        uint32_t* As = sm + cur * 2 * STAGE;
        uint32_t* Ws = As + STAGE;
        #pragma unroll
        for (int ks = 0; ks < KC / 8; ks++) {
            int k8 = ks * 8;
            uint32_t afr[2][4];
            #pragma unroll
            for (int mi = 0; mi < 2; mi++) {
                int rb = wm + mi * 16;
                afr[mi][0] = As[(rb + gid) * LDT + k8 + lig];
                afr[mi][1] = As[(rb + 8 + gid) * LDT + k8 + lig];
                afr[mi][2] = As[(rb + gid) * LDT + k8 + 4 + lig];
                afr[mi][3] = As[(rb + 8 + gid) * LDT + k8 + 4 + lig];
            }
            #pragma unroll
            for (int ni = 0; ni < 4; ni++) {
                uint32_t bfr[2];
                int nb = wn + ni * 8;
                bfr[0] = Ws[(nb + gid) * LDT + k8 + lig];
                bfr[1] = Ws[(nb + gid) * LDT + k8 + 4 + lig];
                mma_tf32(acc[0][ni], afr[0], bfr);
                mma_tf32(acc[1][ni], afr[1], bfr);
            }
        }
        __syncthreads();
    }

    #pragma unroll
    for (int mi = 0; mi < 2; mi++) {
        int rbase = m0 + wm + mi * 16 + gid;
        #pragma unroll
        for (int ni = 0; ni < 4; ni++) {
            int col = n0 + wn + ni * 8 + 2 * lig;
            float bb0 = bias[col], bb1 = bias[col + 1];
            float* p0 = C + (size_t)rbase * Dq + col;
            float* p1 = C + (size_t)(rbase + 8) * Dq + col;
            float2 o0 = {acc[mi][ni][0] + bb0, acc[mi][ni][1] + bb1};
            float2 o1 = {acc[mi][ni][2] + bb0, acc[mi][ni][3] + bb1};
            if (round_c) {
                o0.x = f2tf32f(o0.x); o0.y = f2tf32f(o0.y);
                o1.x = f2tf32f(o1.x); o1.y = f2tf32f(o1.y);
            }
            *(float2*)p0 = o0;
            *(float2*)p1 = o1;
        }
    }
}

// ---------------------------------------------------------------------------
// Fused attention via tf32 mma.sync, cp.async double-buffered K/V (CH=64).
// Operands (g_q/g_k/g_v) already tf32-rounded by the projection epilogue.
// ---------------------------------------------------------------------------
#define SLD 516
#define CH 64
#define KVLD 68
#define KVBUF (CH * KVLD)                   // 4352 floats

#define AOFF_KV  (32 * SLD)                 // 16512
#define AOFF_PXK (AOFF_KV + 2 * KVBUF)      // 25216
#define AOFF_PYK (AOFF_PXK + 512)
#define AOFF_BT  (AOFF_PYK + 512)
#define ATT2_SMEM ((AOFF_BT + 201 + 3) * 4) // ~105.8 KB

__device__ __forceinline__ void ldchunk(float* dst, const float* src, int tid) {
    #pragma unroll
    for (int i = 0; i < 4; i++) {
        int idx = tid + i * 256;
        int r = idx >> 4, c4 = (idx & 15) * 4;
        cp16(&dst[r * KVLD + c4], src + (size_t)r * (Hq * DKq) + c4);
    }
}

__global__ void __launch_bounds__(256) attn_mma(const float* __restrict__ dist_emb,
                                                float* __restrict__ att) {
    float* sm = (float*)dynsm;
    float* S   = sm;
    float* KV0 = sm + AOFF_KV;
    float* KV1 = KV0 + KVBUF;
    float* pxk = sm + AOFF_PXK;
    float* pyk = sm + AOFF_PYK;
    float* bt  = sm + AOFF_BT;

    int bh = blockIdx.y;
    int b = bh / Hq, h = bh - b * Hq;
    int q0 = blockIdx.x * 32;
    int tid = threadIdx.x;
    int wid = tid >> 5, lane = tid & 31;
    int gid = lane >> 2, lig = lane & 3;

    const float* kbase = g_k + ((size_t)(b * Nq) * Hq + h) * DKq;
    const float* vbase = g_v + ((size_t)(b * Nq) * Hq + h) * DKq;

    ldchunk(KV0, kbase, tid);
    cp_commit();

    for (int i = tid; i < Nq; i += 256) {
        pxk[i] = g_px[b * Nq + i];
        pyk[i] = g_py[b * Nq + i];
    }
    for (int i = tid; i < 201; i += 256)
        bt[i] = dist_emb[g_btab[i] * Hq + h];

    float pxr[4], pyr[4];
    #pragma unroll
    for (int i = 0; i < 2; i++)
        #pragma unroll
        for (int half = 0; half < 2; half++) {
            int row = i * 16 + half * 8 + gid;
            pxr[i * 2 + half] = g_px[b * Nq + q0 + row];
            pyr[i * 2 + half] = g_py[b * Nq + q0 + row];
        }

    uint32_t afr[2][8][4];
    #pragma unroll
    for (int i = 0; i < 2; i++) {
        const float* qp  = g_q + ((size_t)((b * Nq + q0 + i * 16 + gid) * Hq + h)) * DKq;
        const float* qp8 = g_q + ((size_t)((b * Nq + q0 + i * 16 + 8 + gid) * Hq + h)) * DKq;
        #pragma unroll
        for (int s = 0; s < 8; s++) {
            afr[i][s][0] = __float_as_uint(qp[s * 8 + lig]);
            afr[i][s][1] = __float_as_uint(qp8[s * 8 + lig]);
            afr[i][s][2] = __float_as_uint(qp[s * 8 + 4 + lig]);
            afr[i][s][3] = __float_as_uint(qp8[s * 8 + 4 + lig]);
        }
    }

    // ---- Phase 1: QK^T ----
    for (int c = 0; c < 8; c++) {
        cp_wait0();
        __syncthreads();
        if (c < 8 - 1) {
            ldchunk((c & 1) ? KV0 : KV1, kbase + (size_t)(c + 1) * CH * Hq * DKq, tid);
            cp_commit();
        }
        const float* KV = (c & 1) ? KV1 : KV0;

        float acc[2][4] = {};
        #pragma unroll
        for (int s = 0; s < 8; s++) {
            uint32_t bfr[2];
            int nrow = 8 * wid + gid;
            bfr[0] = __float_as_uint(KV[nrow * KVLD + s * 8 + lig]);
            bfr[1] = __float_as_uint(KV[nrow * KVLD + s * 8 + 4 + lig]);
            mma_tf32(acc[0], afr[0][s], bfr);
            mma_tf32(acc[1], afr[1][s], bfr);
        }
        #pragma unroll
        for (int i = 0; i < 2; i++)
            #pragma unroll
            for (int idx = 0; idx < 4; idx++) {
                int half = idx >> 1;
                int row = i * 16 + half * 8 + gid;
                int ks = c * CH + 8 * wid + 2 * lig + (idx & 1);
                float dx = pxk[ks] - pxr[i * 2 + half];
                float dy = pyk[ks] - pyr[i * 2 + half];
                int d2 = (int)(dx * dx + dy * dy);
                S[row * SLD + ks] = acc[i][idx] * 0.125f + bt[d2];
            }
    }

    ldchunk(KV0, vbase, tid);
    cp_commit();
    __syncthreads();

    // ---- Phase 2: softmax ----
    #pragma unroll
    for (int rr = 0; rr < 4; rr++) {
        int q = wid * 4 + rr;
        float vals[16];
        float m = -1e30f;
        #pragma unroll
        for (int j = 0; j < 16; j++) {
            vals[j] = S[q * SLD + lane + j * 32];
            m = fmaxf(m, vals[j]);
        }
        #pragma unroll
        for (int o = 16; o > 0; o >>= 1) m = fmaxf(m, __shfl_xor_sync(0xffffffffu, m, o));
        float s = 0.f;
        #pragma unroll
        for (int j = 0; j < 16; j++) {
            vals[j] = __expf(vals[j] - m);
            s += vals[j];
        }
        #pragma unroll
        for (int o = 16; o > 0; o >>= 1) s += __shfl_xor_sync(0xffffffffu, s, o);
        float inv = 1.0f / s;
        float* arow = att + (((size_t)bh) * Nq + q0 + q) * Nq;
        #pragma unroll
        for (int j = 0; j < 16; j++) {
            float v = vals[j] * inv;
            S[q * SLD + lane + j * 32] = f2tf32f(v);
            arow[lane + j * 32] = v;
        }
    }

    // ---- Phase 3: O = S @ V ----
    int mi = wid & 1;
    int nj0 = (wid >> 1) * 2;
    float av[2][4] = {};
    for (int c = 0; c < 8; c++) {
        cp_wait0();
        __syncthreads();
        if (c < 8 - 1) {
            ldchunk((c & 1) ? KV0 : KV1, vbase + (size_t)(c + 1) * CH * Hq * DKq, tid);
            cp_commit();
        }
        const float* KV = (c & 1) ? KV1 : KV0;
        #pragma unroll
        for (int s = 0; s < 8; s++) {
            uint32_t a[4];
            int rbase = (mi * 16 + gid) * SLD + c * CH + s * 8;
            a[0] = __float_as_uint(S[rbase + lig]);
            a[1] = __float_as_uint(S[rbase + 8 * SLD + lig]);
            a[2] = __float_as_uint(S[rbase + 4 + lig]);
            a[3] = __float_as_uint(S[rbase + 8 * SLD + 4 + lig]);
            #pragma unroll
            for (int jj = 0; jj < 2; jj++) {
                int n8 = nj0 + jj;
                uint32_t bfr[2];
                bfr[0] = __float_as_uint(KV[(s * 8 + lig) * KVLD + n8 * 8 + gid]);
                bfr[1] = __float_as_uint(KV[(s * 8 + 4 + lig) * KVLD + n8 * 8 + gid]);
                mma_tf32(av[jj], a, bfr);
            }
        }
    }
    #pragma unroll
    for (int jj = 0; jj < 2; jj++)
        #pragma unroll
        for (int half = 0; half < 2; half++) {
            int row = q0 + mi * 16 + half * 8 + gid;
            int col = (nj0 + jj) * 8 + 2 * lig;
            float2 v;
            v.x = f2tf32f(av[jj][half * 2]);
            v.y = f2tf32f(av[jj][half * 2 + 1]);
            *(float2*)(g_o + ((size_t)((b * Nq + row) * Hq + h)) * DKq + col) = v;
        }
}

// ---------------------------------------------------------------------------
// LayerNorm -> tf32-rounded g_x
// ---------------------------------------------------------------------------
__global__ void __launch_bounds__(256) ln_kernel(const float* __restrict__ f,
                                                 const float* __restrict__ gamma,
                                                 const float* __restrict__ beta) {
    int t = blockIdx.x;
    const float* in = f + (size_t)t * Dq;
    float* out = g_x + (size_t)t * Dq;
    int tid = threadIdx.x;
    float v0 = in[tid], v1 = in[tid + 256], v2 = in[tid + 512];

    __shared__ float red[8];
    __shared__ float bc;

    float s = v0 + v1 + v2;
    #pragma unroll
    for (int o = 16; o > 0; o >>= 1) s += __shfl_down_sync(0xffffffffu, s, o);
    if ((tid & 31) == 0) red[tid >> 5] = s;
    __syncthreads();
    if (tid == 0) {
        float tot = 0.f;
        #pragma unroll
        for (int i = 0; i < 8; i++) tot += red[i];
        bc = tot * (1.0f / 768.0f);
    }
    __syncthreads();
    float mean = bc;
    float d0 = v0 - mean, d1 = v1 - mean, d2 = v2 - mean;
    float ss = d0 * d0 + d1 * d1 + d2 * d2;
    #pragma unroll
    for (int o = 16; o > 0; o >>= 1) ss += __shfl_down_sync(0xffffffffu, ss, o);
    __syncthreads();
    if ((tid & 31) == 0) red[tid >> 5] = ss;
    __syncthreads();
    if (tid == 0) {
        float tot = 0.f;
        #pragma unroll
        for (int i = 0; i < 8; i++) tot += red[i];
        bc = tot * (1.0f / 768.0f);
    }
    __syncthreads();
    float inv = rsqrtf(bc + 1e-5f);
    out[tid]       = f2tf32f(d0 * inv * gamma[tid]       + beta[tid]);
    out[tid + 256] = f2tf32f(d1 * inv * gamma[tid + 256] + beta[tid + 256]);
    out[tid + 512] = f2tf32f(d2 * inv * gamma[tid + 512] + beta[tid + 512]);
}

// ---------------------------------------------------------------------------
// Convert 4 weight matrices to tf32-rounded copies
// ---------------------------------------------------------------------------
__global__ void __launch_bounds__(256) cvtw_kernel(const float* __restrict__ Wq,
                                                   const float* __restrict__ Wk,
                                                   const float* __restrict__ Wv,
                                                   const float* __restrict__ Wo) {
    int i = blockIdx.x * 256 + threadIdx.x;
    if (i >= Dq * Dq) return;
    g_wq[i] = f2tf32f(Wq[i]);
    g_wk[i] = f2tf32f(Wk[i]);
    g_wv[i] = f2tf32f(Wv[i]);
    g_wo[i] = f2tf32f(Wo[i]);
}

// ---------------------------------------------------------------------------
// Patch bins
// ---------------------------------------------------------------------------
__global__ void __launch_bounds__(256) bins_kernel(const float* __restrict__ boxes,
                                                   const int* __restrict__ im) {
    int idx = blockIdx.x * blockDim.x + threadIdx.x;
    if (idx < 201) g_btab[idx] = (int)(2.0 * sqrt((double)idx));
    if (idx >= TOK) return;
    int b = idx / Nq;
    float wf = (float)im[b * 4 + 0];
    float hf = (float)im[b * 4 + 1];
    const float* bx = boxes + (size_t)idx * 4;
    float x1 = bx[0] * wf, y1 = bx[1] * hf, x2 = bx[2] * wf, y2 = bx[3] * hf;
    float spw = floorf(wf / 11.0f), sph = floorf(hf / 11.0f);
    float cx = floorf((x1 + x2) / 2.0f), cy = floorf((y1 + y2) / 2.0f);
    int px = 0, py = 0;
    #pragma unroll
    for (int i = 0; i < 11; i++) {
        float lo = (float)i * spw, hi = (float)(i + 1) * spw;
        if (lo <= cx && cx <= hi) { px = i; break; }
    }
    #pragma unroll
    for (int i = 0; i < 11; i++) {
        float lo = (float)i * sph, hi = (float)(i + 1) * sph;
        if (lo <= cy && cy <= hi) { py = i; break; }
    }
    g_px[idx] = (float)px;
    g_py[idx] = (float)py;
}

// ---------------------------------------------------------------------------
extern "C" void kernel_launch(void* const* d_in, const int* in_sizes, int n_in,
                              void* d_out, int out_size) {
    const float* features = (const float*)d_in[0];
    const float* boxes    = (const float*)d_in[1];
    const int*   im       = (const int*)d_in[2];
    const float* Wq = (const float*)d_in[3];  const float* bqv = (const float*)d_in[4];
    const float* Wk = (const float*)d_in[5];  const float* bkv = (const float*)d_in[6];
    const float* Wv = (const float*)d_in[7];  const float* bvv = (const float*)d_in[8];
    const float* Wo = (const float*)d_in[9];  const float* bov = (const float*)d_in[10];
    const float* gamma = (const float*)d_in[11];
    const float* beta  = (const float*)d_in[12];
    const float* demb  = (const float*)d_in[13];

    float* out = (float*)d_out;
    float* att = out + (size_t)TOK * Dq;

    void *px_, *pq_, *pk_, *pv_, *po_, *pwq_, *pwk_, *pwv_, *pwo_;
    cudaGetSymbolAddress(&px_, g_x);
    cudaGetSymbolAddress(&pq_, g_q);
    cudaGetSymbolAddress(&pk_, g_k);
    cudaGetSymbolAddress(&pv_, g_v);
    cudaGetSymbolAddress(&po_, g_o);
    cudaGetSymbolAddress(&pwq_, g_wq);
    cudaGetSymbolAddress(&pwk_, g_wk);
    cudaGetSymbolAddress(&pwv_, g_wv);
    cudaGetSymbolAddress(&pwo_, g_wo);

    const int GEMM_SMEM = 4 * STAGE * 4;   // 81920 B
    cudaFuncSetAttribute(hmma_gemm, cudaFuncAttributeMaxDynamicSharedMemorySize, GEMM_SMEM);
    cudaFuncSetAttribute(attn_mma, cudaFuncAttributeMaxDynamicSharedMemorySize, ATT2_SMEM);

    ln_kernel<<<TOK, 256>>>(features, gamma, beta);
    bins_kernel<<<(TOK + 255) / 256, 256>>>(boxes, im);
    cvtw_kernel<<<(Dq * Dq + 255) / 256, 256>>>(Wq, Wk, Wv, Wo);

    // QKV projections in one launch; outputs tf32-rounded for attention
    dim3 gqkv(Dq / 128, TOK / 128, 3);
    hmma_gemm<<<gqkv, 512, GEMM_SMEM>>>(
        (const float*)px_,
        (const float*)pwq_, bqv, (float*)pq_,
        (const float*)pwk_, bkv, (float*)pk_,
        (const float*)pwv_, bvv, (float*)pv_, 1);

    // Fused tensor-core attention
    attn_mma<<<dim3(Nq / 32, Bq * Hq), 256, ATT2_SMEM>>>(demb, att);

    // Output projection (NOT rounded — final output)
    dim3 gout(Dq / 128, TOK / 128, 1);
    hmma_gemm<<<gout, 512, GEMM_SMEM>>>(
        (const float*)po_,
        (const float*)pwo_, bov, out,
        (const float*)pwo_, bov, out,
        (const float*)pwo_, bov, out, 0);
}

// round 15
// speedup vs baseline: 3.1480x; 1.2075x over previous
#include <cuda_runtime.h>
#include <math.h>
#include <stdint.h>

#define Bq 16
#define Nq 512
#define Dq 768
#define Hq 12
#define DKq 64
#define TOK (Bq*Nq)   // 8192

// Scratch
__device__ float g_x[TOK*Dq];        // layernormed, tf32-rounded
__device__ float g_q[TOK*Dq];        // (B,N,H,DK) tf32-rounded
__device__ float g_k[TOK*Dq];        // tf32-rounded
__device__ float g_v[TOK*Dq];        // tf32-rounded
__device__ float g_o[TOK*Dq];        // attention out, tf32-rounded
__device__ float g_wq[Dq*Dq];        // tf32-rounded weights
__device__ float g_wk[Dq*Dq];
__device__ float g_wv[Dq*Dq];
__device__ float g_wo[Dq*Dq];
__device__ float g_px[TOK];
__device__ float g_py[TOK];
__device__ int   g_btab[201];

// single dynamic shared buffer shared across kernels
extern __shared__ uint4 dynsm[];

// ---------------------------------------------------------------------------
// helpers
// ---------------------------------------------------------------------------
__device__ __forceinline__ float f2tf32f(float f) {
    uint32_t u;
    asm("cvt.rna.tf32.f32 %0, %1;" : "=r"(u) : "f"(f));
    return __uint_as_float(u);
}
__device__ __forceinline__ void mma_tf32(float c[4], const uint32_t a[4], const uint32_t b[2]) {
    asm volatile(
        "mma.sync.aligned.m16n8k8.row.col.f32.tf32.tf32.f32 "
        "{%0,%1,%2,%3}, {%4,%5,%6,%7}, {%8,%9}, {%0,%1,%2,%3};"
        : "+f"(c[0]), "+f"(c[1]), "+f"(c[2]), "+f"(c[3])
        : "r"(a[0]), "r"(a[1]), "r"(a[2]), "r"(a[3]), "r"(b[0]), "r"(b[1]));
}
__device__ __forceinline__ void cp16(void* smem, const void* g) {
    uint32_t sa = (uint32_t)__cvta_generic_to_shared(smem);
    asm volatile("cp.async.ca.shared.global [%0], [%1], 16;" :: "r"(sa), "l"(g));
}
__device__ __forceinline__ void cp_commit() {
    asm volatile("cp.async.commit_group;" ::: "memory");
}
__device__ __forceinline__ void cp_wait1() {
    asm volatile("cp.async.wait_group 1;" ::: "memory");
}
__device__ __forceinline__ void cp_wait0() {
    asm volatile("cp.async.wait_group 0;" ::: "memory");
}

// ---------------------------------------------------------------------------
// tf32 mma.sync GEMM: C = A @ W^T + bias (+optional tf32 rounding of C)
// CTA tile 128x128, 512 threads, warp grid 4x4 (warp tile 32x32), KC=32,
// cp.async double buffer. LDT=36 -> conflict-free fragment LDS
// (bank = gid*4+lig, perfect 0..31 spread). grid.z selects W/bias/C.
// ---------------------------------------------------------------------------
#define KC 32
#define LDT 36
#define STAGE (128 * LDT)   // uint32s per matrix per stage

__global__ void __launch_bounds__(512, 2) hmma_gemm(
        const float* __restrict__ A0,
        const float* __restrict__ W0, const float* __restrict__ b0, float* __restrict__ C0,
        const float* __restrict__ W1, const float* __restrict__ b1, float* __restrict__ C1,
        const float* __restrict__ W2, const float* __restrict__ b2, float* __restrict__ C2,
        int round_c) {
    uint32_t* sm = (uint32_t*)dynsm;
    int z = blockIdx.z;
    const float* A = A0;
    const float* W = (z == 0) ? W0 : (z == 1) ? W1 : W2;
    const float* bias = (z == 0) ? b0 : (z == 1) ? b1 : b2;
    float* C = (z == 0) ? C0 : (z == 1) ? C1 : C2;

    int tid = threadIdx.x;
    int wid = tid >> 5, lane = tid & 31;
    int wm = (wid >> 2) * 32;          // 4 warp rows
    int wn = (wid & 3) * 32;           // 4 warp cols
    int gid = lane >> 2;
    int lig = lane & 3;
    int m0 = blockIdx.y * 128, n0 = blockIdx.x * 128;

    const float* Ap = A + (size_t)m0 * Dq;
    const float* Wp = W + (size_t)n0 * Dq;

    // fill mapping: 512 threads, 128 rows x 32 floats per matrix
    int lr = tid >> 2;                 // row 0..127
    int lc = (tid & 3) * 8;            // float col 0,8,16,24 (two cp16 each)

    float acc[2][4][4];
    #pragma unroll
    for (int mi = 0; mi < 2; mi++)
        #pragma unroll
        for (int ni = 0; ni < 4; ni++)
            #pragma unroll
            for (int j = 0; j < 4; j++) acc[mi][ni][j] = 0.f;

    {
        uint32_t* As = sm;
        uint32_t* Ws = sm + STAGE;
        cp16(&As[lr * LDT + lc],     Ap + (size_t)lr * Dq + lc);
        cp16(&As[lr * LDT + lc + 4], Ap + (size_t)lr * Dq + lc + 4);
        cp16(&Ws[lr * LDT + lc],     Wp + (size_t)lr * Dq + lc);
        cp16(&Ws[lr * LDT + lc + 4], Wp + (size_t)lr * Dq + lc + 4);
        cp_commit();
    }

    const int NCH = Dq / KC;  // 24
    for (int c = 0; c < NCH; c++) {
        int cur = c & 1;
        if (c + 1 < NCH) {
            uint32_t* As = sm + ((c + 1) & 1) * 2 * STAGE;
            uint32_t* Ws = As + STAGE;
            int k0 = (c + 1) * KC;
            cp16(&As[lr * LDT + lc],     Ap + (size_t)lr * Dq + k0 + lc);
            cp16(&As[lr * LDT + lc + 4], Ap + (size_t)lr * Dq + k0 + lc + 4);
            cp16(&Ws[lr * LDT + lc],     Wp + (size_t)lr * Dq + k0 + lc);
            cp16(&Ws[lr * LDT + lc + 4], Wp + (size_t)lr * Dq + k0 + lc + 4);
            cp_commit();
            cp_wait1();
        } else {
            cp_wait0();
        }
        __syncthreads();
        uint32_t* As = sm + cur * 2 * STAGE;
        uint32_t* Ws = As + STAGE;
        #pragma unroll
        for (int ks = 0; ks < KC / 8; ks++) {
            int k8 = ks * 8;
            uint32_t afr[2][4];
            #pragma unroll
            for (int mi = 0; mi < 2; mi++) {
                int rb = wm + mi * 16;
                afr[mi][0] = As[(rb + gid) * LDT + k8 + lig];
                afr[mi][1] = As[(rb + 8 + gid) * LDT + k8 + lig];
                afr[mi][2] = As[(rb + gid) * LDT + k8 + 4 + lig];
                afr[mi][3] = As[(rb + 8 + gid) * LDT + k8 + 4 + lig];
            }
            #pragma unroll
            for (int ni = 0; ni < 4; ni++) {
                uint32_t bfr[2];
                int nb = wn + ni * 8;
                bfr[0] = Ws[(nb + gid) * LDT + k8 + lig];
                bfr[1] = Ws[(nb + gid) * LDT + k8 + 4 + lig];
                mma_tf32(acc[0][ni], afr[0], bfr);
                mma_tf32(acc[1][ni], afr[1], bfr);
            }
        }
        __syncthreads();
    }

    #pragma unroll
    for (int mi = 0; mi < 2; mi++) {
        int rbase = m0 + wm + mi * 16 + gid;
        #pragma unroll
        for (int ni = 0; ni < 4; ni++) {
            int col = n0 + wn + ni * 8 + 2 * lig;
            float bb0 = bias[col], bb1 = bias[col + 1];
            float* p0 = C + (size_t)rbase * Dq + col;
            float* p1 = C + (size_t)(rbase + 8) * Dq + col;
            float2 o0 = {acc[mi][ni][0] + bb0, acc[mi][ni][1] + bb1};
            float2 o1 = {acc[mi][ni][2] + bb0, acc[mi][ni][3] + bb1};
            if (round_c) {
                o0.x = f2tf32f(o0.x); o0.y = f2tf32f(o0.y);
                o1.x = f2tf32f(o1.x); o1.y = f2tf32f(o1.y);
            }
            *(float2*)p0 = o0;
            *(float2*)p1 = o1;
        }
    }
}

// ---------------------------------------------------------------------------
// Fused attention via tf32 mma.sync, cp.async double-buffered K/V (CH=64).
// K chunks use stride 68 (phase-1 B loads bank = gid*4+lig, conflict-free);
// V chunks use stride 72 (phase-3 B loads bank = lig*8+gid, conflict-free).
// ---------------------------------------------------------------------------
#define SLD 516
#define CH 64
#define KLDs 68
#define VLDs 72
#define KVBUF (CH * VLDs)                   // 4608 floats (max of the two)

#define AOFF_KV  (32 * SLD)                 // 16512
#define AOFF_PXK (AOFF_KV + 2 * KVBUF)      // 25728
#define AOFF_PYK (AOFF_PXK + 512)
#define AOFF_BT  (AOFF_PYK + 512)
#define ATT2_SMEM ((AOFF_BT + 201 + 3) * 4) // ~108 KB

__device__ __forceinline__ void ldchunk(float* dst, const float* src, int tid, int ld) {
    #pragma unroll
    for (int i = 0; i < 4; i++) {
        int idx = tid + i * 256;
        int r = idx >> 4, c4 = (idx & 15) * 4;
        cp16(&dst[r * ld + c4], src + (size_t)r * (Hq * DKq) + c4);
    }
}

__global__ void __launch_bounds__(256) attn_mma(const float* __restrict__ dist_emb,
                                                float* __restrict__ att) {
    float* sm = (float*)dynsm;
    float* S   = sm;
    float* KV0 = sm + AOFF_KV;
    float* KV1 = KV0 + KVBUF;
    float* pxk = sm + AOFF_PXK;
    float* pyk = sm + AOFF_PYK;
    float* bt  = sm + AOFF_BT;

    int bh = blockIdx.y;
    int b = bh / Hq, h = bh - b * Hq;
    int q0 = blockIdx.x * 32;
    int tid = threadIdx.x;
    int wid = tid >> 5, lane = tid & 31;
    int gid = lane >> 2, lig = lane & 3;

    const float* kbase = g_k + ((size_t)(b * Nq) * Hq + h) * DKq;
    const float* vbase = g_v + ((size_t)(b * Nq) * Hq + h) * DKq;

    ldchunk(KV0, kbase, tid, KLDs);
    cp_commit();

    for (int i = tid; i < Nq; i += 256) {
        pxk[i] = g_px[b * Nq + i];
        pyk[i] = g_py[b * Nq + i];
    }
    for (int i = tid; i < 201; i += 256)
        bt[i] = dist_emb[g_btab[i] * Hq + h];

    float pxr[4], pyr[4];
    #pragma unroll
    for (int i = 0; i < 2; i++)
        #pragma unroll
        for (int half = 0; half < 2; half++) {
            int row = i * 16 + half * 8 + gid;
            pxr[i * 2 + half] = g_px[b * Nq + q0 + row];
            pyr[i * 2 + half] = g_py[b * Nq + q0 + row];
        }

    uint32_t afr[2][8][4];
    #pragma unroll
    for (int i = 0; i < 2; i++) {
        const float* qp  = g_q + ((size_t)((b * Nq + q0 + i * 16 + gid) * Hq + h)) * DKq;
        const float* qp8 = g_q + ((size_t)((b * Nq + q0 + i * 16 + 8 + gid) * Hq + h)) * DKq;
        #pragma unroll
        for (int s = 0; s < 8; s++) {
            afr[i][s][0] = __float_as_uint(qp[s * 8 + lig]);
            afr[i][s][1] = __float_as_uint(qp8[s * 8 + lig]);
            afr[i][s][2] = __float_as_uint(qp[s * 8 + 4 + lig]);
            afr[i][s][3] = __float_as_uint(qp8[s * 8 + 4 + lig]);
        }
    }

    // ---- Phase 1: QK^T (K stride KLDs=68) ----
    for (int c = 0; c < 8; c++) {
        cp_wait0();
        __syncthreads();
        if (c < 8 - 1) {
            ldchunk((c & 1) ? KV0 : KV1, kbase + (size_t)(c + 1) * CH * Hq * DKq, tid, KLDs);
            cp_commit();
        }
        const float* KV = (c & 1) ? KV1 : KV0;

        float acc[2][4] = {};
        #pragma unroll
        for (int s = 0; s < 8; s++) {
            uint32_t bfr[2];
            int nrow = 8 * wid + gid;
            bfr[0] = __float_as_uint(KV[nrow * KLDs + s * 8 + lig]);
            bfr[1] = __float_as_uint(KV[nrow * KLDs + s * 8 + 4 + lig]);
            mma_tf32(acc[0], afr[0][s], bfr);
            mma_tf32(acc[1], afr[1][s], bfr);
        }
        #pragma unroll
        for (int i = 0; i < 2; i++)
            #pragma unroll
            for (int idx = 0; idx < 4; idx++) {
                int half = idx >> 1;
                int row = i * 16 + half * 8 + gid;
                int ks = c * CH + 8 * wid + 2 * lig + (idx & 1);
                float dx = pxk[ks] - pxr[i * 2 + half];
                float dy = pyk[ks] - pyr[i * 2 + half];
                int d2 = (int)(dx * dx + dy * dy);
                S[row * SLD + ks] = acc[i][idx] * 0.125f + bt[d2];
            }
    }

    ldchunk(KV0, vbase, tid, VLDs);
    cp_commit();
    __syncthreads();

    // ---- Phase 2: softmax ----
    #pragma unroll
    for (int rr = 0; rr < 4; rr++) {
        int q = wid * 4 + rr;
        float vals[16];
        float m = -1e30f;
        #pragma unroll
        for (int j = 0; j < 16; j++) {
            vals[j] = S[q * SLD + lane + j * 32];
            m = fmaxf(m, vals[j]);
        }
        #pragma unroll
        for (int o = 16; o > 0; o >>= 1) m = fmaxf(m, __shfl_xor_sync(0xffffffffu, m, o));
        float s = 0.f;
        #pragma unroll
        for (int j = 0; j < 16; j++) {
            vals[j] = __expf(vals[j] - m);
            s += vals[j];
        }
        #pragma unroll
        for (int o = 16; o > 0; o >>= 1) s += __shfl_xor_sync(0xffffffffu, s, o);
        float inv = 1.0f / s;
        float* arow = att + (((size_t)bh) * Nq + q0 + q) * Nq;
        #pragma unroll
        for (int j = 0; j < 16; j++) {
            float v = vals[j] * inv;
            S[q * SLD + lane + j * 32] = f2tf32f(v);
            arow[lane + j * 32] = v;
        }
    }

    // ---- Phase 3: O = S @ V (V stride VLDs=72) ----
    int mi = wid & 1;
    int nj0 = (wid >> 1) * 2;
    float av[2][4] = {};
    for (int c = 0; c < 8; c++) {
        cp_wait0();
        __syncthreads();
        if (c < 8 - 1) {
            ldchunk((c & 1) ? KV0 : KV1, vbase + (size_t)(c + 1) * CH * Hq * DKq, tid, VLDs);
            cp_commit();
        }
        const float* KV = (c & 1) ? KV1 : KV0;
        #pragma unroll
        for (int s = 0; s < 8; s++) {
            uint32_t a[4];
            int rbase = (mi * 16 + gid) * SLD + c * CH + s * 8;
            a[0] = __float_as_uint(S[rbase + lig]);
            a[1] = __float_as_uint(S[rbase + 8 * SLD + lig]);
            a[2] = __float_as_uint(S[rbase + 4 + lig]);
            a[3] = __float_as_uint(S[rbase + 8 * SLD + 4 + lig]);
            #pragma unroll
            for (int jj = 0; jj < 2; jj++) {
                int n8 = nj0 + jj;
                uint32_t bfr[2];
                bfr[0] = __float_as_uint(KV[(s * 8 + lig) * VLDs + n8 * 8 + gid]);
                bfr[1] = __float_as_uint(KV[(s * 8 + 4 + lig) * VLDs + n8 * 8 + gid]);
                mma_tf32(av[jj], a, bfr);
            }
        }
    }
    #pragma unroll
    for (int jj = 0; jj < 2; jj++)
        #pragma unroll
        for (int half = 0; half < 2; half++) {
            int row = q0 + mi * 16 + half * 8 + gid;
            int col = (nj0 + jj) * 8 + 2 * lig;
            float2 v;
            v.x = f2tf32f(av[jj][half * 2]);
            v.y = f2tf32f(av[jj][half * 2 + 1]);
            *(float2*)(g_o + ((size_t)((b * Nq + row) * Hq + h)) * DKq + col) = v;
        }
}

// ---------------------------------------------------------------------------
// LayerNorm -> tf32-rounded g_x
// ---------------------------------------------------------------------------
__global__ void __launch_bounds__(256) ln_kernel(const float* __restrict__ f,
                                                 const float* __restrict__ gamma,
                                                 const float* __restrict__ beta) {
    int t = blockIdx.x;
    const float* in = f + (size_t)t * Dq;
    float* out = g_x + (size_t)t * Dq;
    int tid = threadIdx.x;
    float v0 = in[tid], v1 = in[tid + 256], v2 = in[tid + 512];

    __shared__ float red[8];
    __shared__ float bc;

    float s = v0 + v1 + v2;
    #pragma unroll
    for (int o = 16; o > 0; o >>= 1) s += __shfl_down_sync(0xffffffffu, s, o);
    if ((tid & 31) == 0) red[tid >> 5] = s;
    __syncthreads();
    if (tid == 0) {
        float tot = 0.f;
        #pragma unroll
        for (int i = 0; i < 8; i++) tot += red[i];
        bc = tot * (1.0f / 768.0f);
    }
    __syncthreads();
    float mean = bc;
    float d0 = v0 - mean, d1 = v1 - mean, d2 = v2 - mean;
    float ss = d0 * d0 + d1 * d1 + d2 * d2;
    #pragma unroll
    for (int o = 16; o > 0; o >>= 1) ss += __shfl_down_sync(0xffffffffu, ss, o);
    __syncthreads();
    if ((tid & 31) == 0) red[tid >> 5] = ss;
    __syncthreads();
    if (tid == 0) {
        float tot = 0.f;
        #pragma unroll
        for (int i = 0; i < 8; i++) tot += red[i];
        bc = tot * (1.0f / 768.0f);
    }
    __syncthreads();
    float inv = rsqrtf(bc + 1e-5f);
    out[tid]       = f2tf32f(d0 * inv * gamma[tid]       + beta[tid]);
    out[tid + 256] = f2tf32f(d1 * inv * gamma[tid + 256] + beta[tid + 256]);
    out[tid + 512] = f2tf32f(d2 * inv * gamma[tid + 512] + beta[tid + 512]);
}

// ---------------------------------------------------------------------------
// Convert 4 weight matrices to tf32-rounded copies
// ---------------------------------------------------------------------------
__global__ void __launch_bounds__(256) cvtw_kernel(const float* __restrict__ Wq,
                                                   const float* __restrict__ Wk,
                                                   const float* __restrict__ Wv,
                                                   const float* __restrict__ Wo) {
    int i = blockIdx.x * 256 + threadIdx.x;
    if (i >= Dq * Dq) return;
    g_wq[i] = f2tf32f(Wq[i]);
    g_wk[i] = f2tf32f(Wk[i]);
    g_wv[i] = f2tf32f(Wv[i]);
    g_wo[i] = f2tf32f(Wo[i]);
}

// ---------------------------------------------------------------------------
// Patch bins
// ---------------------------------------------------------------------------
__global__ void __launch_bounds__(256) bins_kernel(const float* __restrict__ boxes,
                                                   const int* __restrict__ im) {
    int idx = blockIdx.x * blockDim.x + threadIdx.x;
    if (idx < 201) g_btab[idx] = (int)(2.0 * sqrt((double)idx));
    if (idx >= TOK) return;
    int b = idx / Nq;
    float wf = (float)im[b * 4 + 0];
    float hf = (float)im[b * 4 + 1];
    const float* bx = boxes + (size_t)idx * 4;
    float x1 = bx[0] * wf, y1 = bx[1] * hf, x2 = bx[2] * wf, y2 = bx[3] * hf;
    float spw = floorf(wf / 11.0f), sph = floorf(hf / 11.0f);
    float cx = floorf((x1 + x2) / 2.0f), cy = floorf((y1 + y2) / 2.0f);
    int px = 0, py = 0;
    #pragma unroll
    for (int i = 0; i < 11; i++) {
        float lo = (float)i * spw, hi = (float)(i + 1) * spw;
        if (lo <= cx && cx <= hi) { px = i; break; }
    }
    #pragma unroll
    for (int i = 0; i < 11; i++) {
        float lo = (float)i * sph, hi = (float)(i + 1) * sph;
        if (lo <= cy && cy <= hi) { py = i; break; }
    }
    g_px[idx] = (float)px;
    g_py[idx] = (float)py;
}

// ---------------------------------------------------------------------------
extern "C" void kernel_launch(void* const* d_in, const int* in_sizes, int n_in,
                              void* d_out, int out_size) {
    const float* features = (const float*)d_in[0];
    const float* boxes    = (const float*)d_in[1];
    const int*   im       = (const int*)d_in[2];
    const float* Wq = (const float*)d_in[3];  const float* bqv = (const float*)d_in[4];
    const float* Wk = (const float*)d_in[5];  const float* bkv = (const float*)d_in[6];
    const float* Wv = (const float*)d_in[7];  const float* bvv = (const float*)d_in[8];
    const float* Wo = (const float*)d_in[9];  const float* bov = (const float*)d_in[10];
    const float* gamma = (const float*)d_in[11];
    const float* beta  = (const float*)d_in[12];
    const float* demb  = (const float*)d_in[13];

    float* out = (float*)d_out;
    float* att = out + (size_t)TOK * Dq;

    void *px_, *pq_, *pk_, *pv_, *po_, *pwq_, *pwk_, *pwv_, *pwo_;
    cudaGetSymbolAddress(&px_, g_x);
    cudaGetSymbolAddress(&pq_, g_q);
    cudaGetSymbolAddress(&pk_, g_k);
    cudaGetSymbolAddress(&pv_, g_v);
    cudaGetSymbolAddress(&po_, g_o);
    cudaGetSymbolAddress(&pwq_, g_wq);
    cudaGetSymbolAddress(&pwk_, g_wk);
    cudaGetSymbolAddress(&pwv_, g_wv);
    cudaGetSymbolAddress(&pwo_, g_wo);

    const int GEMM_SMEM = 4 * STAGE * 4;   // 73728 B
    cudaFuncSetAttribute(hmma_gemm, cudaFuncAttributeMaxDynamicSharedMemorySize, GEMM_SMEM);
    cudaFuncSetAttribute(attn_mma, cudaFuncAttributeMaxDynamicSharedMemorySize, ATT2_SMEM);

    ln_kernel<<<TOK, 256>>>(features, gamma, beta);
    bins_kernel<<<(TOK + 255) / 256, 256>>>(boxes, im);
    cvtw_kernel<<<(Dq * Dq + 255) / 256, 256>>>(Wq, Wk, Wv, Wo);

    // QKV projections in one launch; outputs tf32-rounded for attention
    dim3 gqkv(Dq / 128, TOK / 128, 3);
    hmma_gemm<<<gqkv, 512, GEMM_SMEM>>>(
        (const float*)px_,
        (const float*)pwq_, bqv, (float*)pq_,
        (const float*)pwk_, bkv, (float*)pk_,
        (const float*)pwv_, bvv, (float*)pv_, 1);

    // Fused tensor-core attention
    attn_mma<<<dim3(Nq / 32, Bq * Hq), 256, ATT2_SMEM>>>(demb, att);

    // Output projection (NOT rounded — final output)
    dim3 gout(Dq / 128, TOK / 128, 1);
    hmma_gemm<<<gout, 512, GEMM_SMEM>>>(
        (const float*)po_,
        (const float*)pwo_, bov, out,
        (const float*)pwo_, bov, out,
        (const float*)pwo_, bov, out, 0);
}